// round 1
// baseline (speedup 1.0000x reference)
#include <cuda_runtime.h>

#define EDIM 1024
#define NH   16
#define HD   64
#define NB   4
#define SEQ  2048
#define MTOT (NB*SEQ)   // 8192 rows

// Scratch (device globals: allocation-free per harness rules). 4 x 32 MB.
__device__ float g_q[(size_t)MTOT * EDIM];
__device__ float g_k[(size_t)MTOT * EDIM];
__device__ float g_v[(size_t)MTOT * EDIM];
__device__ float g_o[(size_t)MTOT * EDIM];

// ---------------------------------------------------------------------------
// SGEMM: C[M,N] = A[M,K] * W[N,K]^T (+ bias[N]).  Both A and W are K-major,
// so both smem tiles load with float4 along K and store transposed.
// 128x128 block tile, BK=8, 256 threads, 8x8 register micro-tile,
// double-buffered shared memory.
// ---------------------------------------------------------------------------
template<bool HAS_BIAS>
__global__ __launch_bounds__(256, 2)
void sgemm_nt(const float* __restrict__ A, const float* __restrict__ W,
              const float* __restrict__ bias, float* __restrict__ C,
              int M, int N, int K)
{
    __shared__ float sA[2][8][132];
    __shared__ float sB[2][8][132];

    const int tid  = threadIdx.x;
    const int lr   = tid >> 1;          // 0..127 : row within tile
    const int lk   = (tid & 1) << 2;    // 0 or 4 : k offset
    const int row0 = blockIdx.y * 128;
    const int col0 = blockIdx.x * 128;

    const float* ap = A + (size_t)(row0 + lr) * K + lk;
    const float* bp = W + (size_t)(col0 + lr) * K + lk;

    float4 fa = *(const float4*)ap;
    float4 fb = *(const float4*)bp;
    sA[0][lk + 0][lr] = fa.x; sA[0][lk + 1][lr] = fa.y;
    sA[0][lk + 2][lr] = fa.z; sA[0][lk + 3][lr] = fa.w;
    sB[0][lk + 0][lr] = fb.x; sB[0][lk + 1][lr] = fb.y;
    sB[0][lk + 2][lr] = fb.z; sB[0][lk + 3][lr] = fb.w;
    __syncthreads();

    const int ty = tid >> 4;   // 0..15
    const int tx = tid & 15;   // 0..15

    float acc[8][8];
#pragma unroll
    for (int i = 0; i < 8; i++)
#pragma unroll
        for (int j = 0; j < 8; j++) acc[i][j] = 0.f;

    const int nkt = K >> 3;
    int buf = 0;
    for (int kt = 1; kt <= nkt; kt++) {
        if (kt < nkt) {
            fa = *(const float4*)(ap + (size_t)kt * 8);
            fb = *(const float4*)(bp + (size_t)kt * 8);
        }
#pragma unroll
        for (int k = 0; k < 8; k++) {
            float a[8], b[8];
            *(float4*)&a[0] = *(const float4*)&sA[buf][k][ty * 4];
            *(float4*)&a[4] = *(const float4*)&sA[buf][k][64 + ty * 4];
            *(float4*)&b[0] = *(const float4*)&sB[buf][k][tx * 4];
            *(float4*)&b[4] = *(const float4*)&sB[buf][k][64 + tx * 4];
#pragma unroll
            for (int i = 0; i < 8; i++)
#pragma unroll
                for (int j = 0; j < 8; j++)
                    acc[i][j] = fmaf(a[i], b[j], acc[i][j]);
        }
        if (kt < nkt) {
            buf ^= 1;
            sA[buf][lk + 0][lr] = fa.x; sA[buf][lk + 1][lr] = fa.y;
            sA[buf][lk + 2][lr] = fa.z; sA[buf][lk + 3][lr] = fa.w;
            sB[buf][lk + 0][lr] = fb.x; sB[buf][lk + 1][lr] = fb.y;
            sB[buf][lk + 2][lr] = fb.z; sB[buf][lk + 3][lr] = fb.w;
            __syncthreads();
        }
    }

#pragma unroll
    for (int i = 0; i < 8; i++) {
        int r = row0 + ((i < 4) ? (ty * 4 + i) : (64 + ty * 4 + i - 4));
#pragma unroll
        for (int jh = 0; jh < 2; jh++) {
            int c = col0 + jh * 64 + tx * 4;
            float4 ov;
            ov.x = acc[i][jh * 4 + 0];
            ov.y = acc[i][jh * 4 + 1];
            ov.z = acc[i][jh * 4 + 2];
            ov.w = acc[i][jh * 4 + 3];
            if (HAS_BIAS) {
                ov.x += bias[c + 0]; ov.y += bias[c + 1];
                ov.z += bias[c + 2]; ov.w += bias[c + 3];
            }
            *(float4*)(C + (size_t)r * N + c) = ov;
        }
    }
}

// ---------------------------------------------------------------------------
// Flash attention, fp32, faithful to the reference bug: softmax over the
// UNSCALED scores q.k (no 1/sqrt(D)).
// Br = Bc = 128, D = 64. 256 threads. One CTA per (q-tile, head, batch).
// Smem: Qs[d][i] 64x128, Ks[d][j] 64x128, Vs[j][dd] 128x68(pad), Ps[i][j]
// 128x132(pad).  Per-thread: scores 8x8, O accum 8x4, row stats x8.
// ---------------------------------------------------------------------------
#define FA_SMEM_FLOATS (8192 + 8192 + 128*68 + 128*132)   // 41984
#define FA_SMEM_BYTES  (FA_SMEM_FLOATS * 4)               // 167936

__global__ __launch_bounds__(256, 1)
void flash_attn_kernel(const float* __restrict__ q, const float* __restrict__ k,
                       const float* __restrict__ v, float* __restrict__ o)
{
    extern __shared__ float smem[];
    float* sQ = smem;                       // [64][128]
    float* sK = smem + 8192;                // [64][128]
    float* sV = smem + 16384;               // [128][68]
    float* sP = smem + 16384 + 128 * 68;    // [128][132]

    const int tid  = threadIdx.x;
    const int ty   = tid >> 4;     // 0..15 row group
    const int tx   = tid & 15;     // 0..15 col group
    const int lr   = tid >> 1;     // 0..127 loader row
    const int half = tid & 1;      // loader k/d half

    const int qt = blockIdx.x;     // q tile
    const int h  = blockIdx.y;
    const int b  = blockIdx.z;

    const size_t baseRow = (size_t)b * SEQ;
    const int hcol = h * HD;

    // Load Q tile transposed into sQ[d][i]
    {
        const float* qp = q + (baseRow + qt * 128 + lr) * EDIM + hcol + half * 32;
#pragma unroll
        for (int cc = 0; cc < 8; cc++) {
            float4 t = *(const float4*)(qp + cc * 4);
            int d = half * 32 + cc * 4;
            sQ[(d + 0) * 128 + lr] = t.x;
            sQ[(d + 1) * 128 + lr] = t.y;
            sQ[(d + 2) * 128 + lr] = t.z;
            sQ[(d + 3) * 128 + lr] = t.w;
        }
    }

    float oacc[8][4];
    float mrow[8], lrow[8];
#pragma unroll
    for (int r = 0; r < 8; r++) {
        mrow[r] = -1e30f;
        lrow[r] = 0.f;
#pragma unroll
        for (int c = 0; c < 4; c++) oacc[r][c] = 0.f;
    }

    for (int t = 0; t < SEQ / 128; t++) {
        // Prefetch K/V tile to registers (gmem latency hidden behind the
        // barrier that drains the previous iteration's PV).
        float4 kf[8], vf[8];
        {
            const float* kp = k + (baseRow + t * 128 + lr) * EDIM + hcol + half * 32;
            const float* vp = v + (baseRow + t * 128 + lr) * EDIM + hcol + half * 32;
#pragma unroll
            for (int cc = 0; cc < 8; cc++) {
                kf[cc] = *(const float4*)(kp + cc * 4);
                vf[cc] = *(const float4*)(vp + cc * 4);
            }
        }
        __syncthreads();   // previous PV reads of sV/sP done (and Q store at t=0)

        // Store K transposed, V direct
#pragma unroll
        for (int cc = 0; cc < 8; cc++) {
            int d = half * 32 + cc * 4;
            sK[(d + 0) * 128 + lr] = kf[cc].x;
            sK[(d + 1) * 128 + lr] = kf[cc].y;
            sK[(d + 2) * 128 + lr] = kf[cc].z;
            sK[(d + 3) * 128 + lr] = kf[cc].w;
            *(float4*)(sV + lr * 68 + half * 32 + cc * 4) = vf[cc];
        }
        __syncthreads();

        // S = Q K^T  (128x128x64)
        float s[8][8];
#pragma unroll
        for (int r = 0; r < 8; r++)
#pragma unroll
            for (int c = 0; c < 8; c++) s[r][c] = 0.f;

#pragma unroll 8
        for (int d = 0; d < 64; d++) {
            float a[8], bb[8];
            *(float4*)&a[0]  = *(const float4*)(sQ + d * 128 + ty * 4);
            *(float4*)&a[4]  = *(const float4*)(sQ + d * 128 + 64 + ty * 4);
            *(float4*)&bb[0] = *(const float4*)(sK + d * 128 + tx * 4);
            *(float4*)&bb[4] = *(const float4*)(sK + d * 128 + 64 + tx * 4);
#pragma unroll
            for (int r = 0; r < 8; r++)
#pragma unroll
                for (int c = 0; c < 8; c++)
                    s[r][c] = fmaf(a[r], bb[c], s[r][c]);
        }

        // Online softmax (row stats replicated across the 16 tx lanes)
#pragma unroll
        for (int r = 0; r < 8; r++) {
            float mx = s[r][0];
#pragma unroll
            for (int c = 1; c < 8; c++) mx = fmaxf(mx, s[r][c]);
#pragma unroll
            for (int off = 8; off >= 1; off >>= 1)
                mx = fmaxf(mx, __shfl_xor_sync(0xffffffffu, mx, off));
            float mnew  = fmaxf(mrow[r], mx);
            float alpha = __expf(mrow[r] - mnew);
            mrow[r] = mnew;
            float sum = 0.f;
#pragma unroll
            for (int c = 0; c < 8; c++) {
                s[r][c] = __expf(s[r][c] - mnew);
                sum += s[r][c];
            }
#pragma unroll
            for (int off = 8; off >= 1; off >>= 1)
                sum += __shfl_xor_sync(0xffffffffu, sum, off);
            lrow[r] = lrow[r] * alpha + sum;
#pragma unroll
            for (int c = 0; c < 4; c++) oacc[r][c] *= alpha;
        }

        // P -> smem (row-major, padded stride 132; float4 both ways)
#pragma unroll
        for (int r = 0; r < 8; r++) {
            int i = (r < 4) ? (ty * 4 + r) : (64 + ty * 4 + r - 4);
            *(float4*)(sP + i * 132 + tx * 4)      = make_float4(s[r][0], s[r][1], s[r][2], s[r][3]);
            *(float4*)(sP + i * 132 + 64 + tx * 4) = make_float4(s[r][4], s[r][5], s[r][6], s[r][7]);
        }
        __syncthreads();

        // O += P V   (128x64x128), j processed in blocks of 4
#pragma unroll 4
        for (int jb = 0; jb < 32; jb++) {
            int j = jb * 4;
            float4 v0 = *(const float4*)(sV + (j + 0) * 68 + tx * 4);
            float4 v1 = *(const float4*)(sV + (j + 1) * 68 + tx * 4);
            float4 v2 = *(const float4*)(sV + (j + 2) * 68 + tx * 4);
            float4 v3 = *(const float4*)(sV + (j + 3) * 68 + tx * 4);
#pragma unroll
            for (int r = 0; r < 8; r++) {
                int i = (r < 4) ? (ty * 4 + r) : (64 + ty * 4 + r - 4);
                float4 p = *(const float4*)(sP + i * 132 + j);
                oacc[r][0] += p.x * v0.x + p.y * v1.x + p.z * v2.x + p.w * v3.x;
                oacc[r][1] += p.x * v0.y + p.y * v1.y + p.z * v2.y + p.w * v3.y;
                oacc[r][2] += p.x * v0.z + p.y * v1.z + p.z * v2.z + p.w * v3.z;
                oacc[r][3] += p.x * v0.w + p.y * v1.w + p.z * v2.w + p.w * v3.w;
            }
        }
    }

    // Normalize and write out ([B,S,H,D] packed == [B,S,E])
#pragma unroll
    for (int r = 0; r < 8; r++) {
        int i = (r < 4) ? (ty * 4 + r) : (64 + ty * 4 + r - 4);
        float inv = 1.0f / lrow[r];
        float4 res;
        res.x = oacc[r][0] * inv;
        res.y = oacc[r][1] * inv;
        res.z = oacc[r][2] * inv;
        res.w = oacc[r][3] * inv;
        *(float4*)(o + (baseRow + qt * 128 + i) * EDIM + hcol + tx * 4) = res;
    }
}

// ---------------------------------------------------------------------------
extern "C" void kernel_launch(void* const* d_in, const int* in_sizes, int n_in,
                              void* d_out, int out_size)
{
    (void)in_sizes; (void)n_in; (void)out_size;

    const float* Q  = (const float*)d_in[0];
    const float* K  = (const float*)d_in[1];
    const float* V  = (const float*)d_in[2];
    const float* Wq = (const float*)d_in[3];
    const float* Wk = (const float*)d_in[4];
    const float* Wv = (const float*)d_in[5];
    const float* Wo = (const float*)d_in[6];
    const float* bo = (const float*)d_in[7];
    float* out = (float*)d_out;

    float *gq, *gk, *gv, *go;
    cudaGetSymbolAddress((void**)&gq, g_q);
    cudaGetSymbolAddress((void**)&gk, g_k);
    cudaGetSymbolAddress((void**)&gv, g_v);
    cudaGetSymbolAddress((void**)&go, g_o);

    dim3 gemmGrid(EDIM / 128, MTOT / 128);

    sgemm_nt<false><<<gemmGrid, 256>>>(Q, Wq, nullptr, gq, MTOT, EDIM, EDIM);
    sgemm_nt<false><<<gemmGrid, 256>>>(K, Wk, nullptr, gk, MTOT, EDIM, EDIM);
    sgemm_nt<false><<<gemmGrid, 256>>>(V, Wv, nullptr, gv, MTOT, EDIM, EDIM);

    cudaFuncSetAttribute(flash_attn_kernel,
                         cudaFuncAttributeMaxDynamicSharedMemorySize,
                         FA_SMEM_BYTES);
    flash_attn_kernel<<<dim3(SEQ / 128, NH, NB), 256, FA_SMEM_BYTES>>>(gq, gk, gv, go);

    sgemm_nt<true><<<gemmGrid, 256>>>(go, Wo, bo, out, MTOT, EDIM, EDIM);
}

// round 3
// speedup vs baseline: 1.3353x; 1.3353x over previous
#include <cuda_runtime.h>
#include <cuda_bf16.h>
#include <cstdint>

#define EDIM 1024
#define NH   16
#define HD   64
#define NB   4
#define SEQ  2048
#define MTOT (NB*SEQ)   // 8192 rows

// Scratch (device globals: allocation-free per harness rules). 4 x 32 MB.
__device__ float g_q[(size_t)MTOT * EDIM];
__device__ float g_k[(size_t)MTOT * EDIM];
__device__ float g_v[(size_t)MTOT * EDIM];
__device__ float g_o[(size_t)MTOT * EDIM];

// ---------------------------------------------------------------------------
// helpers
// ---------------------------------------------------------------------------
__device__ __forceinline__ uint32_t smem_u32(const void* p) {
    uint32_t a;
    asm("{ .reg .u64 t; cvta.to.shared.u64 t, %1; cvt.u32.u64 %0, t; }"
        : "=r"(a) : "l"(p));
    return a;
}

__device__ __forceinline__ void ldsm_x4(uint32_t* r, uint32_t addr) {
    asm volatile("ldmatrix.sync.aligned.m8n8.x4.shared.b16 {%0,%1,%2,%3}, [%4];"
                 : "=r"(r[0]), "=r"(r[1]), "=r"(r[2]), "=r"(r[3]) : "r"(addr));
}

__device__ __forceinline__ void mma16816(float* d, const uint32_t* a,
                                         const uint32_t* b) {
    asm volatile(
        "mma.sync.aligned.m16n8k16.row.col.f32.bf16.bf16.f32 "
        "{%0,%1,%2,%3}, {%4,%5,%6,%7}, {%8,%9}, {%0,%1,%2,%3};"
        : "+f"(d[0]), "+f"(d[1]), "+f"(d[2]), "+f"(d[3])
        : "r"(a[0]), "r"(a[1]), "r"(a[2]), "r"(a[3]), "r"(b[0]), "r"(b[1]));
}

// ---------------------------------------------------------------------------
// HMMA GEMM: C[M,1024] = A[M,1024] * W[1024,1024]^T (+ bias), fp32-accurate
// via in-kernel 2-way bf16 split and 3 MMA products (A1B1 + A1B2 + A2B1).
// CTA tile 128x128, BK=32, 256 threads (8 warps: 4 along M x 2 along N),
// warp tile 32x64, double-buffered smem.
// Smem rows: 32 bf16 + 8 pad = 40 elems = 80 B  -> ldmatrix conflict-free.
// ---------------------------------------------------------------------------
#define BK          32
#define ROWB        80                    // bytes per smem row
#define TILEB       (128 * ROWB)          // 10240 B, one split tile
#define STAGEB      (4 * TILEB)           // A1,A2,B1,B2 = 40960 B
#define GEMM_SMEM   (2 * STAGEB)          // 81920 B

__device__ __forceinline__ void split_store(char* smem, uint32_t off_hi,
                                            uint32_t off_lo, float4 v) {
    float in[4] = {v.x, v.y, v.z, v.w};
    __nv_bfloat16 hi[4], lo[4];
#pragma unroll
    for (int i = 0; i < 4; i++) {
        hi[i] = __float2bfloat16_rn(in[i]);
        lo[i] = __float2bfloat16_rn(in[i] - __bfloat162float(hi[i]));
    }
    __nv_bfloat162 h0 = __halves2bfloat162(hi[0], hi[1]);
    __nv_bfloat162 h1 = __halves2bfloat162(hi[2], hi[3]);
    __nv_bfloat162 l0 = __halves2bfloat162(lo[0], lo[1]);
    __nv_bfloat162 l1 = __halves2bfloat162(lo[2], lo[3]);
    *(uint2*)(smem + off_hi) = make_uint2(
        *reinterpret_cast<uint32_t*>(&h0), *reinterpret_cast<uint32_t*>(&h1));
    *(uint2*)(smem + off_lo) = make_uint2(
        *reinterpret_cast<uint32_t*>(&l0), *reinterpret_cast<uint32_t*>(&l1));
}

template<bool HAS_BIAS>
__global__ __launch_bounds__(256, 1)
void gemm_hmma(const float* __restrict__ A, const float* __restrict__ W,
               const float* __restrict__ bias, float* __restrict__ C)
{
    extern __shared__ char smem[];
    const uint32_t sb = smem_u32(smem);
    const int tid  = threadIdx.x;
    const int wid  = tid >> 5;
    const int lane = tid & 31;
    const int row0 = blockIdx.y * 128;
    const int col0 = blockIdx.x * 128;
    const int warp_m = (wid & 3) * 32;    // 0,32,64,96
    const int warp_n = (wid >> 2) * 64;   // 0,64

    const float* ag = A + (size_t)row0 * EDIM;
    const float* bg = W + (size_t)col0 * EDIM;

    // ldmatrix per-lane offsets (within a tile, bytes)
    const uint32_t a_loff = (uint32_t)(lane & 15) * ROWB + ((lane & 16) ? 16u : 0u);
    const uint32_t b_loff = (uint32_t)((lane & 7) + ((lane & 16) ? 8 : 0)) * ROWB
                          + ((lane & 8) ? 16u : 0u);

    // ---- load stage 0 ----
    float4 fa[4], fb[4];
#pragma unroll
    for (int it = 0; it < 4; it++) {
        int c = tid + it * 256;
        fa[it] = *(const float4*)(ag + (size_t)(c >> 3) * EDIM + (c & 7) * 4);
        fb[it] = *(const float4*)(bg + (size_t)(c >> 3) * EDIM + (c & 7) * 4);
    }
#pragma unroll
    for (int it = 0; it < 4; it++) {
        int c = tid + it * 256;
        uint32_t off = (uint32_t)(c >> 3) * ROWB + (uint32_t)(c & 7) * 8;
        split_store(smem, off, off + TILEB, fa[it]);
        split_store(smem, off + 2 * TILEB, off + 3 * TILEB, fb[it]);
    }
    __syncthreads();

    float acc[2][8][4];
#pragma unroll
    for (int mt = 0; mt < 2; mt++)
#pragma unroll
        for (int nt = 0; nt < 8; nt++)
#pragma unroll
            for (int i = 0; i < 4; i++) acc[mt][nt][i] = 0.f;

    const int NKT = EDIM / BK;   // 32
    for (int kt = 1; kt <= NKT; kt++) {
        if (kt < NKT) {
#pragma unroll
            for (int it = 0; it < 4; it++) {
                int c = tid + it * 256;
                fa[it] = *(const float4*)(ag + (size_t)(c >> 3) * EDIM + kt * BK + (c & 7) * 4);
                fb[it] = *(const float4*)(bg + (size_t)(c >> 3) * EDIM + kt * BK + (c & 7) * 4);
            }
        }

        const uint32_t base = sb + (uint32_t)((kt - 1) & 1) * STAGEB;
#pragma unroll
        for (int ks = 0; ks < 2; ks++) {
            const uint32_t koff = ks * 32;   // 16 bf16 = 32 bytes
            uint32_t afr[2][2][4];           // [split][mtile]
#pragma unroll
            for (int sp = 0; sp < 2; sp++)
#pragma unroll
                for (int mt = 0; mt < 2; mt++)
                    ldsm_x4(afr[sp][mt],
                            base + sp * TILEB + (uint32_t)(warp_m + mt * 16) * ROWB
                                 + koff + a_loff);
            uint32_t bfr[2][4][4];           // [split][npair]  (x4 = two n-tiles)
#pragma unroll
            for (int sp = 0; sp < 2; sp++)
#pragma unroll
                for (int np = 0; np < 4; np++)
                    ldsm_x4(bfr[sp][np],
                            base + (2 + sp) * TILEB + (uint32_t)(warp_n + np * 16) * ROWB
                                 + koff + b_loff);
#pragma unroll
            for (int mt = 0; mt < 2; mt++)
#pragma unroll
                for (int np = 0; np < 4; np++) {
                    mma16816(acc[mt][2 * np + 0], afr[0][mt], &bfr[0][np][0]);
                    mma16816(acc[mt][2 * np + 1], afr[0][mt], &bfr[0][np][2]);
                    mma16816(acc[mt][2 * np + 0], afr[0][mt], &bfr[1][np][0]);
                    mma16816(acc[mt][2 * np + 1], afr[0][mt], &bfr[1][np][2]);
                    mma16816(acc[mt][2 * np + 0], afr[1][mt], &bfr[0][np][0]);
                    mma16816(acc[mt][2 * np + 1], afr[1][mt], &bfr[0][np][2]);
                }
        }

        if (kt < NKT) {
            const uint32_t dst = (uint32_t)(kt & 1) * STAGEB;
#pragma unroll
            for (int it = 0; it < 4; it++) {
                int c = tid + it * 256;
                uint32_t off = dst + (uint32_t)(c >> 3) * ROWB + (uint32_t)(c & 7) * 8;
                split_store(smem, off, off + TILEB, fa[it]);
                split_store(smem, off + 2 * TILEB, off + 3 * TILEB, fb[it]);
            }
            __syncthreads();
        }
    }

    // ---- epilogue ----
    const int g   = lane >> 2;
    const int tig = lane & 3;
#pragma unroll
    for (int mt = 0; mt < 2; mt++) {
        int r = row0 + warp_m + mt * 16 + g;
#pragma unroll
        for (int nt = 0; nt < 8; nt++) {
            int col = col0 + warp_n + nt * 8 + 2 * tig;
            float bx = 0.f, by = 0.f;
            if (HAS_BIAS) { bx = bias[col]; by = bias[col + 1]; }
            *(float2*)(C + (size_t)r * EDIM + col) =
                make_float2(acc[mt][nt][0] + bx, acc[mt][nt][1] + by);
            *(float2*)(C + (size_t)(r + 8) * EDIM + col) =
                make_float2(acc[mt][nt][2] + bx, acc[mt][nt][3] + by);
        }
    }
}

// ---------------------------------------------------------------------------
// Flash attention, fp32 (unchanged): softmax over UNSCALED q.k.
// ---------------------------------------------------------------------------
#define FA_SMEM_FLOATS (8192 + 8192 + 128*68 + 128*132)
#define FA_SMEM_BYTES  (FA_SMEM_FLOATS * 4)

__global__ __launch_bounds__(256, 1)
void flash_attn_kernel(const float* __restrict__ q, const float* __restrict__ k,
                       const float* __restrict__ v, float* __restrict__ o)
{
    extern __shared__ float smemf[];
    float* sQ = smemf;
    float* sK = smemf + 8192;
    float* sV = smemf + 16384;
    float* sP = smemf + 16384 + 128 * 68;

    const int tid  = threadIdx.x;
    const int ty   = tid >> 4;
    const int tx   = tid & 15;
    const int lr   = tid >> 1;
    const int half = tid & 1;

    const int qt = blockIdx.x;
    const int h  = blockIdx.y;
    const int b  = blockIdx.z;

    const size_t baseRow = (size_t)b * SEQ;
    const int hcol = h * HD;

    {
        const float* qp = q + (baseRow + qt * 128 + lr) * EDIM + hcol + half * 32;
#pragma unroll
        for (int cc = 0; cc < 8; cc++) {
            float4 t = *(const float4*)(qp + cc * 4);
            int d = half * 32 + cc * 4;
            sQ[(d + 0) * 128 + lr] = t.x;
            sQ[(d + 1) * 128 + lr] = t.y;
            sQ[(d + 2) * 128 + lr] = t.z;
            sQ[(d + 3) * 128 + lr] = t.w;
        }
    }

    float oacc[8][4];
    float mrow[8], lrow[8];
#pragma unroll
    for (int r = 0; r < 8; r++) {
        mrow[r] = -1e30f;
        lrow[r] = 0.f;
#pragma unroll
        for (int c = 0; c < 4; c++) oacc[r][c] = 0.f;
    }

    for (int t = 0; t < SEQ / 128; t++) {
        float4 kf[8], vf[8];
        {
            const float* kp = k + (baseRow + t * 128 + lr) * EDIM + hcol + half * 32;
            const float* vp = v + (baseRow + t * 128 + lr) * EDIM + hcol + half * 32;
#pragma unroll
            for (int cc = 0; cc < 8; cc++) {
                kf[cc] = *(const float4*)(kp + cc * 4);
                vf[cc] = *(const float4*)(vp + cc * 4);
            }
        }
        __syncthreads();

#pragma unroll
        for (int cc = 0; cc < 8; cc++) {
            int d = half * 32 + cc * 4;
            sK[(d + 0) * 128 + lr] = kf[cc].x;
            sK[(d + 1) * 128 + lr] = kf[cc].y;
            sK[(d + 2) * 128 + lr] = kf[cc].z;
            sK[(d + 3) * 128 + lr] = kf[cc].w;
            *(float4*)(sV + lr * 68 + half * 32 + cc * 4) = vf[cc];
        }
        __syncthreads();

        float s[8][8];
#pragma unroll
        for (int r = 0; r < 8; r++)
#pragma unroll
            for (int c = 0; c < 8; c++) s[r][c] = 0.f;

#pragma unroll 8
        for (int d = 0; d < 64; d++) {
            float a[8], bb[8];
            *(float4*)&a[0]  = *(const float4*)(sQ + d * 128 + ty * 4);
            *(float4*)&a[4]  = *(const float4*)(sQ + d * 128 + 64 + ty * 4);
            *(float4*)&bb[0] = *(const float4*)(sK + d * 128 + tx * 4);
            *(float4*)&bb[4] = *(const float4*)(sK + d * 128 + 64 + tx * 4);
#pragma unroll
            for (int r = 0; r < 8; r++)
#pragma unroll
                for (int c = 0; c < 8; c++)
                    s[r][c] = fmaf(a[r], bb[c], s[r][c]);
        }

#pragma unroll
        for (int r = 0; r < 8; r++) {
            float mx = s[r][0];
#pragma unroll
            for (int c = 1; c < 8; c++) mx = fmaxf(mx, s[r][c]);
#pragma unroll
            for (int off = 8; off >= 1; off >>= 1)
                mx = fmaxf(mx, __shfl_xor_sync(0xffffffffu, mx, off));
            float mnew  = fmaxf(mrow[r], mx);
            float alpha = __expf(mrow[r] - mnew);
            mrow[r] = mnew;
            float sum = 0.f;
#pragma unroll
            for (int c = 0; c < 8; c++) {
                s[r][c] = __expf(s[r][c] - mnew);
                sum += s[r][c];
            }
#pragma unroll
            for (int off = 8; off >= 1; off >>= 1)
                sum += __shfl_xor_sync(0xffffffffu, sum, off);
            lrow[r] = lrow[r] * alpha + sum;
#pragma unroll
            for (int c = 0; c < 4; c++) oacc[r][c] *= alpha;
        }

#pragma unroll
        for (int r = 0; r < 8; r++) {
            int i = (r < 4) ? (ty * 4 + r) : (64 + ty * 4 + r - 4);
            *(float4*)(sP + i * 132 + tx * 4)      = make_float4(s[r][0], s[r][1], s[r][2], s[r][3]);
            *(float4*)(sP + i * 132 + 64 + tx * 4) = make_float4(s[r][4], s[r][5], s[r][6], s[r][7]);
        }
        __syncthreads();

#pragma unroll 4
        for (int jb = 0; jb < 32; jb++) {
            int j = jb * 4;
            float4 v0 = *(const float4*)(sV + (j + 0) * 68 + tx * 4);
            float4 v1 = *(const float4*)(sV + (j + 1) * 68 + tx * 4);
            float4 v2 = *(const float4*)(sV + (j + 2) * 68 + tx * 4);
            float4 v3 = *(const float4*)(sV + (j + 3) * 68 + tx * 4);
#pragma unroll
            for (int r = 0; r < 8; r++) {
                int i = (r < 4) ? (ty * 4 + r) : (64 + ty * 4 + r - 4);
                float4 p = *(const float4*)(sP + i * 132 + j);
                oacc[r][0] += p.x * v0.x + p.y * v1.x + p.z * v2.x + p.w * v3.x;
                oacc[r][1] += p.x * v0.y + p.y * v1.y + p.z * v2.y + p.w * v3.y;
                oacc[r][2] += p.x * v0.z + p.y * v1.z + p.z * v2.z + p.w * v3.z;
                oacc[r][3] += p.x * v0.w + p.y * v1.w + p.z * v2.w + p.w * v3.w;
            }
        }
    }

#pragma unroll
    for (int r = 0; r < 8; r++) {
        int i = (r < 4) ? (ty * 4 + r) : (64 + ty * 4 + r - 4);
        float inv = 1.0f / lrow[r];
        float4 res;
        res.x = oacc[r][0] * inv;
        res.y = oacc[r][1] * inv;
        res.z = oacc[r][2] * inv;
        res.w = oacc[r][3] * inv;
        *(float4*)(o + (baseRow + qt * 128 + i) * EDIM + hcol + tx * 4) = res;
    }
}

// ---------------------------------------------------------------------------
extern "C" void kernel_launch(void* const* d_in, const int* in_sizes, int n_in,
                              void* d_out, int out_size)
{
    (void)in_sizes; (void)n_in; (void)out_size;

    const float* Q  = (const float*)d_in[0];
    const float* K  = (const float*)d_in[1];
    const float* V  = (const float*)d_in[2];
    const float* Wq = (const float*)d_in[3];
    const float* Wk = (const float*)d_in[4];
    const float* Wv = (const float*)d_in[5];
    const float* Wo = (const float*)d_in[6];
    const float* bo = (const float*)d_in[7];
    float* out = (float*)d_out;

    float *gq, *gk, *gv, *go;
    cudaGetSymbolAddress((void**)&gq, g_q);
    cudaGetSymbolAddress((void**)&gk, g_k);
    cudaGetSymbolAddress((void**)&gv, g_v);
    cudaGetSymbolAddress((void**)&go, g_o);

    cudaFuncSetAttribute(gemm_hmma<false>,
                         cudaFuncAttributeMaxDynamicSharedMemorySize, GEMM_SMEM);
    cudaFuncSetAttribute(gemm_hmma<true>,
                         cudaFuncAttributeMaxDynamicSharedMemorySize, GEMM_SMEM);
    cudaFuncSetAttribute(flash_attn_kernel,
                         cudaFuncAttributeMaxDynamicSharedMemorySize, FA_SMEM_BYTES);

    dim3 gemmGrid(EDIM / 128, MTOT / 128);   // (8, 64)

    gemm_hmma<false><<<gemmGrid, 256, GEMM_SMEM>>>(Q, Wq, nullptr, gq);
    gemm_hmma<false><<<gemmGrid, 256, GEMM_SMEM>>>(K, Wk, nullptr, gk);
    gemm_hmma<false><<<gemmGrid, 256, GEMM_SMEM>>>(V, Wv, nullptr, gv);

    flash_attn_kernel<<<dim3(SEQ / 128, NH, NB), 256, FA_SMEM_BYTES>>>(gq, gk, gv, go);

    gemm_hmma<true><<<gemmGrid, 256, GEMM_SMEM>>>(go, Wo, bo, out);
}

// round 4
// speedup vs baseline: 2.1615x; 1.6187x over previous
#include <cuda_runtime.h>
#include <cuda_bf16.h>
#include <cstdint>

#define EDIM 1024
#define NH   16
#define HD   64
#define NB   4
#define SEQ  2048
#define MTOT (NB*SEQ)   // 8192 rows

// Scratch (device globals: allocation-free per harness rules). 4 x 32 MB.
__device__ float g_q[(size_t)MTOT * EDIM];
__device__ float g_k[(size_t)MTOT * EDIM];
__device__ float g_v[(size_t)MTOT * EDIM];
__device__ float g_o[(size_t)MTOT * EDIM];

// ---------------------------------------------------------------------------
// helpers
// ---------------------------------------------------------------------------
__device__ __forceinline__ uint32_t smem_u32(const void* p) {
    uint32_t a;
    asm("{ .reg .u64 t; cvta.to.shared.u64 t, %1; cvt.u32.u64 %0, t; }"
        : "=r"(a) : "l"(p));
    return a;
}

__device__ __forceinline__ void ldsm_x4(uint32_t* r, uint32_t addr) {
    asm volatile("ldmatrix.sync.aligned.m8n8.x4.shared.b16 {%0,%1,%2,%3}, [%4];"
                 : "=r"(r[0]), "=r"(r[1]), "=r"(r[2]), "=r"(r[3]) : "r"(addr));
}

__device__ __forceinline__ void mma16816(float* d, const uint32_t* a,
                                         const uint32_t* b) {
    asm volatile(
        "mma.sync.aligned.m16n8k16.row.col.f32.bf16.bf16.f32 "
        "{%0,%1,%2,%3}, {%4,%5,%6,%7}, {%8,%9}, {%0,%1,%2,%3};"
        : "+f"(d[0]), "+f"(d[1]), "+f"(d[2]), "+f"(d[3])
        : "r"(a[0]), "r"(a[1]), "r"(a[2]), "r"(a[3]), "r"(b[0]), "r"(b[1]));
}

__device__ __forceinline__ uint32_t pack_bf16x2(float x, float y) {
    __nv_bfloat162 t = __halves2bfloat162(__float2bfloat16_rn(x),
                                          __float2bfloat16_rn(y));
    return *reinterpret_cast<uint32_t*>(&t);
}

// ---------------------------------------------------------------------------
// HMMA GEMM (unchanged from R3): C = A * W^T (+bias), 2-way bf16 split,
// 3 products. CTA tile 128x128, BK=32, 8 warps.
// ---------------------------------------------------------------------------
#define BK          32
#define ROWB        80
#define TILEB       (128 * ROWB)
#define STAGEB      (4 * TILEB)
#define GEMM_SMEM   (2 * STAGEB)

__device__ __forceinline__ void split_store(char* smem, uint32_t off_hi,
                                            uint32_t off_lo, float4 v) {
    float in[4] = {v.x, v.y, v.z, v.w};
    __nv_bfloat16 hi[4], lo[4];
#pragma unroll
    for (int i = 0; i < 4; i++) {
        hi[i] = __float2bfloat16_rn(in[i]);
        lo[i] = __float2bfloat16_rn(in[i] - __bfloat162float(hi[i]));
    }
    __nv_bfloat162 h0 = __halves2bfloat162(hi[0], hi[1]);
    __nv_bfloat162 h1 = __halves2bfloat162(hi[2], hi[3]);
    __nv_bfloat162 l0 = __halves2bfloat162(lo[0], lo[1]);
    __nv_bfloat162 l1 = __halves2bfloat162(lo[2], lo[3]);
    *(uint2*)(smem + off_hi) = make_uint2(
        *reinterpret_cast<uint32_t*>(&h0), *reinterpret_cast<uint32_t*>(&h1));
    *(uint2*)(smem + off_lo) = make_uint2(
        *reinterpret_cast<uint32_t*>(&l0), *reinterpret_cast<uint32_t*>(&l1));
}

template<bool HAS_BIAS>
__global__ __launch_bounds__(256, 1)
void gemm_hmma(const float* __restrict__ A, const float* __restrict__ W,
               const float* __restrict__ bias, float* __restrict__ C)
{
    extern __shared__ char smem[];
    const uint32_t sb = smem_u32(smem);
    const int tid  = threadIdx.x;
    const int wid  = tid >> 5;
    const int lane = tid & 31;
    const int row0 = blockIdx.y * 128;
    const int col0 = blockIdx.x * 128;
    const int warp_m = (wid & 3) * 32;
    const int warp_n = (wid >> 2) * 64;

    const float* ag = A + (size_t)row0 * EDIM;
    const float* bg = W + (size_t)col0 * EDIM;

    const uint32_t a_loff = (uint32_t)(lane & 15) * ROWB + ((lane & 16) ? 16u : 0u);
    const uint32_t b_loff = (uint32_t)((lane & 7) + ((lane & 16) ? 8 : 0)) * ROWB
                          + ((lane & 8) ? 16u : 0u);

    float4 fa[4], fb[4];
#pragma unroll
    for (int it = 0; it < 4; it++) {
        int c = tid + it * 256;
        fa[it] = *(const float4*)(ag + (size_t)(c >> 3) * EDIM + (c & 7) * 4);
        fb[it] = *(const float4*)(bg + (size_t)(c >> 3) * EDIM + (c & 7) * 4);
    }
#pragma unroll
    for (int it = 0; it < 4; it++) {
        int c = tid + it * 256;
        uint32_t off = (uint32_t)(c >> 3) * ROWB + (uint32_t)(c & 7) * 8;
        split_store(smem, off, off + TILEB, fa[it]);
        split_store(smem, off + 2 * TILEB, off + 3 * TILEB, fb[it]);
    }
    __syncthreads();

    float acc[2][8][4];
#pragma unroll
    for (int mt = 0; mt < 2; mt++)
#pragma unroll
        for (int nt = 0; nt < 8; nt++)
#pragma unroll
            for (int i = 0; i < 4; i++) acc[mt][nt][i] = 0.f;

    const int NKT = EDIM / BK;
    for (int kt = 1; kt <= NKT; kt++) {
        if (kt < NKT) {
#pragma unroll
            for (int it = 0; it < 4; it++) {
                int c = tid + it * 256;
                fa[it] = *(const float4*)(ag + (size_t)(c >> 3) * EDIM + kt * BK + (c & 7) * 4);
                fb[it] = *(const float4*)(bg + (size_t)(c >> 3) * EDIM + kt * BK + (c & 7) * 4);
            }
        }

        const uint32_t base = sb + (uint32_t)((kt - 1) & 1) * STAGEB;
#pragma unroll
        for (int ks = 0; ks < 2; ks++) {
            const uint32_t koff = ks * 32;
            uint32_t afr[2][2][4];
#pragma unroll
            for (int sp = 0; sp < 2; sp++)
#pragma unroll
                for (int mt = 0; mt < 2; mt++)
                    ldsm_x4(afr[sp][mt],
                            base + sp * TILEB + (uint32_t)(warp_m + mt * 16) * ROWB
                                 + koff + a_loff);
            uint32_t bfr[2][4][4];
#pragma unroll
            for (int sp = 0; sp < 2; sp++)
#pragma unroll
                for (int np = 0; np < 4; np++)
                    ldsm_x4(bfr[sp][np],
                            base + (2 + sp) * TILEB + (uint32_t)(warp_n + np * 16) * ROWB
                                 + koff + b_loff);
#pragma unroll
            for (int mt = 0; mt < 2; mt++)
#pragma unroll
                for (int np = 0; np < 4; np++) {
                    mma16816(acc[mt][2 * np + 0], afr[0][mt], &bfr[0][np][0]);
                    mma16816(acc[mt][2 * np + 1], afr[0][mt], &bfr[0][np][2]);
                    mma16816(acc[mt][2 * np + 0], afr[0][mt], &bfr[1][np][0]);
                    mma16816(acc[mt][2 * np + 1], afr[0][mt], &bfr[1][np][2]);
                    mma16816(acc[mt][2 * np + 0], afr[1][mt], &bfr[0][np][0]);
                    mma16816(acc[mt][2 * np + 1], afr[1][mt], &bfr[0][np][2]);
                }
        }

        if (kt < NKT) {
            const uint32_t dst = (uint32_t)(kt & 1) * STAGEB;
#pragma unroll
            for (int it = 0; it < 4; it++) {
                int c = tid + it * 256;
                uint32_t off = dst + (uint32_t)(c >> 3) * ROWB + (uint32_t)(c & 7) * 8;
                split_store(smem, off, off + TILEB, fa[it]);
                split_store(smem, off + 2 * TILEB, off + 3 * TILEB, fb[it]);
            }
            __syncthreads();
        }
    }

    const int g   = lane >> 2;
    const int tig = lane & 3;
#pragma unroll
    for (int mt = 0; mt < 2; mt++) {
        int r = row0 + warp_m + mt * 16 + g;
#pragma unroll
        for (int nt = 0; nt < 8; nt++) {
            int col = col0 + warp_n + nt * 8 + 2 * tig;
            float bx = 0.f, by = 0.f;
            if (HAS_BIAS) { bx = bias[col]; by = bias[col + 1]; }
            *(float2*)(C + (size_t)r * EDIM + col) =
                make_float2(acc[mt][nt][0] + bx, acc[mt][nt][1] + by);
            *(float2*)(C + (size_t)(r + 8) * EDIM + col) =
                make_float2(acc[mt][nt][2] + bx, acc[mt][nt][3] + by);
        }
    }
}

// ---------------------------------------------------------------------------
// Flash attention on HMMA. Softmax over UNSCALED scores (faithful to the
// reference bug), single-pass without running max (scores bounded; exp fits
// fp32 with huge headroom, and softmax is shift-invariant so this is exact).
// Br=128 (CTA), Bc=128 per iteration, D=64. 8 warps x 16 q-rows.
// QK^T and P*V both via 2-way bf16 split, 3 products.
// P goes accumulator->registers->A-fragments directly (no smem round trip).
// ---------------------------------------------------------------------------
#define KROWB  144                   // 64 bf16 + 16B pad
#define KTILE  (128 * KROWB)         // 18432
#define VROWB  272                   // 128 bf16 + 16B pad
#define VTILE  (64 * VROWB)          // 17408
#define FA2_SMEM (2 * KTILE + 2 * VTILE)   // 71680

__global__ __launch_bounds__(256, 1)
void flash_hmma(const float* __restrict__ q, const float* __restrict__ k,
                const float* __restrict__ v, float* __restrict__ o)
{
    extern __shared__ char sm[];
    const uint32_t sb = smem_u32(sm);
    const int tid  = threadIdx.x;
    const int wid  = tid >> 5;
    const int lane = tid & 31;
    const int lr   = tid >> 1;        // loader row 0..127
    const int half = tid & 1;         // loader d-half
    const int warp_m = wid * 16;

    const int qt = blockIdx.x;
    const int h  = blockIdx.y;
    const int b  = blockIdx.z;
    const size_t baseRow = (size_t)b * SEQ;
    const int hcol = h * HD;

    const uint32_t a_loff  = (uint32_t)(lane & 15) * KROWB + ((lane & 16) ? 16u : 0u);
    const uint32_t bk_loff = (uint32_t)((lane & 7) + ((lane & 16) ? 8 : 0)) * KROWB
                           + ((lane & 8) ? 16u : 0u);
    const uint32_t bv_loff = (uint32_t)((lane & 7) + ((lane & 16) ? 8 : 0)) * VROWB
                           + ((lane & 8) ? 16u : 0u);

    // ---- stage Q through the K smem area, pull A-fragments to registers ----
    uint32_t qfr[2][4][4];   // [split][kstep][frag]
    {
        const float* qp = q + (baseRow + qt * 128 + lr) * EDIM + hcol + half * 32;
#pragma unroll
        for (int cc = 0; cc < 8; cc++) {
            float4 t = *(const float4*)(qp + cc * 4);
            uint32_t off = (uint32_t)lr * KROWB + (uint32_t)(half * 32 + cc * 4) * 2;
            split_store(sm, off, off + KTILE, t);
        }
        __syncthreads();
#pragma unroll
        for (int sp = 0; sp < 2; sp++)
#pragma unroll
            for (int ks = 0; ks < 4; ks++)
                ldsm_x4(qfr[sp][ks],
                        sb + sp * KTILE + (uint32_t)warp_m * KROWB + ks * 32 + a_loff);
    }

    float Oa[8][4];
#pragma unroll
    for (int i = 0; i < 8; i++)
#pragma unroll
        for (int c = 0; c < 4; c++) Oa[i][c] = 0.f;
    float l0 = 0.f, l1 = 0.f;

    for (int t = 0; t < SEQ / 128; t++) {
        // prefetch K/V tile to registers
        float4 kf[8], vf[8];
        {
            const float* kp = k + (baseRow + t * 128 + lr) * EDIM + hcol + half * 32;
            const float* vp = v + (baseRow + t * 128 + lr) * EDIM + hcol + half * 32;
#pragma unroll
            for (int cc = 0; cc < 8; cc++) {
                kf[cc] = *(const float4*)(kp + cc * 4);
                vf[cc] = *(const float4*)(vp + cc * 4);
            }
        }
        __syncthreads();   // previous iteration's ldsm done (Q frags at t=0)

        // K split store (rows n, d contiguous)
#pragma unroll
        for (int cc = 0; cc < 8; cc++) {
            uint32_t off = (uint32_t)lr * KROWB + (uint32_t)(half * 32 + cc * 4) * 2;
            split_store(sm, off, off + KTILE, kf[cc]);
        }
        // V^T split store (rows d, n contiguous) — scalar bf16 scatter
#pragma unroll
        for (int cc = 0; cc < 8; cc++) {
            float in[4] = {vf[cc].x, vf[cc].y, vf[cc].z, vf[cc].w};
#pragma unroll
            for (int j = 0; j < 4; j++) {
                int d = half * 32 + cc * 4 + j;
                __nv_bfloat16 hi = __float2bfloat16_rn(in[j]);
                __nv_bfloat16 lo = __float2bfloat16_rn(in[j] - __bfloat162float(hi));
                uint32_t off = 2 * KTILE + (uint32_t)d * VROWB + (uint32_t)lr * 2;
                *reinterpret_cast<__nv_bfloat16*>(sm + off) = hi;
                *reinterpret_cast<__nv_bfloat16*>(sm + off + VTILE) = lo;
            }
        }
        __syncthreads();

        // ---- S = Q K^T : warp computes 16 x 128 ----
        float S[8][2][4];
#pragma unroll
        for (int ng = 0; ng < 8; ng++) {
#pragma unroll
            for (int tt = 0; tt < 2; tt++)
#pragma unroll
                for (int c = 0; c < 4; c++) S[ng][tt][c] = 0.f;
#pragma unroll
            for (int ks = 0; ks < 4; ks++) {
                uint32_t b1[4], b2[4];
                ldsm_x4(b1, sb + (uint32_t)(ng * 16) * KROWB + ks * 32 + bk_loff);
                ldsm_x4(b2, sb + KTILE + (uint32_t)(ng * 16) * KROWB + ks * 32 + bk_loff);
                mma16816(S[ng][0], qfr[0][ks], &b1[0]);
                mma16816(S[ng][1], qfr[0][ks], &b1[2]);
                mma16816(S[ng][0], qfr[0][ks], &b2[0]);
                mma16816(S[ng][1], qfr[0][ks], &b2[2]);
                mma16816(S[ng][0], qfr[1][ks], &b1[0]);
                mma16816(S[ng][1], qfr[1][ks], &b1[2]);
            }
        }

        // ---- exp (no max shift) + row sums ----
        float rs0 = 0.f, rs1 = 0.f;
#pragma unroll
        for (int ng = 0; ng < 8; ng++)
#pragma unroll
            for (int tt = 0; tt < 2; tt++) {
                S[ng][tt][0] = __expf(S[ng][tt][0]);
                S[ng][tt][1] = __expf(S[ng][tt][1]);
                S[ng][tt][2] = __expf(S[ng][tt][2]);
                S[ng][tt][3] = __expf(S[ng][tt][3]);
                rs0 += S[ng][tt][0] + S[ng][tt][1];
                rs1 += S[ng][tt][2] + S[ng][tt][3];
            }
        rs0 += __shfl_xor_sync(0xffffffffu, rs0, 1);
        rs0 += __shfl_xor_sync(0xffffffffu, rs0, 2);
        rs1 += __shfl_xor_sync(0xffffffffu, rs1, 1);
        rs1 += __shfl_xor_sync(0xffffffffu, rs1, 2);
        l0 += rs0;
        l1 += rs1;

        // ---- O += P V : P split in registers, V split from smem ----
#pragma unroll
        for (int kk = 0; kk < 8; kk++) {
            uint32_t p1[4], p2[4];
#pragma unroll
            for (int tt = 0; tt < 2; tt++) {
#pragma unroll
                for (int hl = 0; hl < 2; hl++) {
                    float x = S[kk][tt][2 * hl + 0];
                    float y = S[kk][tt][2 * hl + 1];
                    __nv_bfloat16 hx = __float2bfloat16_rn(x);
                    __nv_bfloat16 hy = __float2bfloat16_rn(y);
                    __nv_bfloat162 hp = __halves2bfloat162(hx, hy);
                    p1[tt * 2 + hl] = *reinterpret_cast<uint32_t*>(&hp);
                    __nv_bfloat162 lp = __halves2bfloat162(
                        __float2bfloat16_rn(x - __bfloat162float(hx)),
                        __float2bfloat16_rn(y - __bfloat162float(hy)));
                    p2[tt * 2 + hl] = *reinterpret_cast<uint32_t*>(&lp);
                }
            }
            // frag order: a0=(row g,k0-7)=S[kk][0][0..1], a1=(g+8,k0-7)=S[kk][0][2..3],
            //             a2=(g,k8-15)=S[kk][1][0..1], a3=(g+8,k8-15)=S[kk][1][2..3]
            uint32_t A1[4] = {p1[0], p1[1], p1[2], p1[3]};
            uint32_t A2[4] = {p2[0], p2[1], p2[2], p2[3]};
#pragma unroll
            for (int dg = 0; dg < 4; dg++) {
                uint32_t v1[4], v2[4];
                uint32_t vb = sb + 2 * KTILE + (uint32_t)(dg * 16) * VROWB + kk * 32 + bv_loff;
                ldsm_x4(v1, vb);
                ldsm_x4(v2, vb + VTILE);
                mma16816(Oa[dg * 2 + 0], A1, &v1[0]);
                mma16816(Oa[dg * 2 + 1], A1, &v1[2]);
                mma16816(Oa[dg * 2 + 0], A1, &v2[0]);
                mma16816(Oa[dg * 2 + 1], A1, &v2[2]);
                mma16816(Oa[dg * 2 + 0], A2, &v1[0]);
                mma16816(Oa[dg * 2 + 1], A2, &v1[2]);
            }
        }
    }

    // ---- normalize & write ----
    const int g   = lane >> 2;
    const int tq2 = (lane & 3) * 2;
    const float inv0 = 1.0f / l0;
    const float inv1 = 1.0f / l1;
    float* op0 = o + (baseRow + qt * 128 + warp_m + g) * EDIM + hcol;
    float* op1 = op0 + (size_t)8 * EDIM;
#pragma unroll
    for (int i = 0; i < 8; i++) {
        int d = i * 8 + tq2;
        *(float2*)(op0 + d) = make_float2(Oa[i][0] * inv0, Oa[i][1] * inv0);
        *(float2*)(op1 + d) = make_float2(Oa[i][2] * inv1, Oa[i][3] * inv1);
    }
}

// ---------------------------------------------------------------------------
extern "C" void kernel_launch(void* const* d_in, const int* in_sizes, int n_in,
                              void* d_out, int out_size)
{
    (void)in_sizes; (void)n_in; (void)out_size;

    const float* Q  = (const float*)d_in[0];
    const float* K  = (const float*)d_in[1];
    const float* V  = (const float*)d_in[2];
    const float* Wq = (const float*)d_in[3];
    const float* Wk = (const float*)d_in[4];
    const float* Wv = (const float*)d_in[5];
    const float* Wo = (const float*)d_in[6];
    const float* bo = (const float*)d_in[7];
    float* out = (float*)d_out;

    float *gq, *gk, *gv, *go;
    cudaGetSymbolAddress((void**)&gq, g_q);
    cudaGetSymbolAddress((void**)&gk, g_k);
    cudaGetSymbolAddress((void**)&gv, g_v);
    cudaGetSymbolAddress((void**)&go, g_o);

    cudaFuncSetAttribute(gemm_hmma<false>,
                         cudaFuncAttributeMaxDynamicSharedMemorySize, GEMM_SMEM);
    cudaFuncSetAttribute(gemm_hmma<true>,
                         cudaFuncAttributeMaxDynamicSharedMemorySize, GEMM_SMEM);
    cudaFuncSetAttribute(flash_hmma,
                         cudaFuncAttributeMaxDynamicSharedMemorySize, FA2_SMEM);

    dim3 gemmGrid(EDIM / 128, MTOT / 128);

    gemm_hmma<false><<<gemmGrid, 256, GEMM_SMEM>>>(Q, Wq, nullptr, gq);
    gemm_hmma<false><<<gemmGrid, 256, GEMM_SMEM>>>(K, Wk, nullptr, gk);
    gemm_hmma<false><<<gemmGrid, 256, GEMM_SMEM>>>(V, Wv, nullptr, gv);

    flash_hmma<<<dim3(SEQ / 128, NH, NB), 256, FA2_SMEM>>>(gq, gk, gv, go);

    gemm_hmma<true><<<gemmGrid, 256, GEMM_SMEM>>>(go, Wo, bo, out);
}

// round 5
// speedup vs baseline: 2.2012x; 1.0184x over previous
#include <cuda_runtime.h>
#include <cuda_bf16.h>
#include <cstdint>

#define EDIM 1024
#define NH   16
#define HD   64
#define NB   4
#define SEQ  2048
#define MTOT (NB*SEQ)   // 8192 rows

// Scratch (device globals: allocation-free per harness rules). 4 x 32 MB.
__device__ float g_q[(size_t)MTOT * EDIM];
__device__ float g_k[(size_t)MTOT * EDIM];
__device__ float g_v[(size_t)MTOT * EDIM];
__device__ float g_o[(size_t)MTOT * EDIM];

// ---------------------------------------------------------------------------
// helpers
// ---------------------------------------------------------------------------
__device__ __forceinline__ uint32_t smem_u32(const void* p) {
    uint32_t a;
    asm("{ .reg .u64 t; cvta.to.shared.u64 t, %1; cvt.u32.u64 %0, t; }"
        : "=r"(a) : "l"(p));
    return a;
}

__device__ __forceinline__ void ldsm_x4(uint32_t* r, uint32_t addr) {
    asm volatile("ldmatrix.sync.aligned.m8n8.x4.shared.b16 {%0,%1,%2,%3}, [%4];"
                 : "=r"(r[0]), "=r"(r[1]), "=r"(r[2]), "=r"(r[3]) : "r"(addr));
}

__device__ __forceinline__ void ldsm_x4_t(uint32_t* r, uint32_t addr) {
    asm volatile("ldmatrix.sync.aligned.m8n8.x4.trans.shared.b16 {%0,%1,%2,%3}, [%4];"
                 : "=r"(r[0]), "=r"(r[1]), "=r"(r[2]), "=r"(r[3]) : "r"(addr));
}

__device__ __forceinline__ void mma16816(float* d, const uint32_t* a,
                                         const uint32_t* b) {
    asm volatile(
        "mma.sync.aligned.m16n8k16.row.col.f32.bf16.bf16.f32 "
        "{%0,%1,%2,%3}, {%4,%5,%6,%7}, {%8,%9}, {%0,%1,%2,%3};"
        : "+f"(d[0]), "+f"(d[1]), "+f"(d[2]), "+f"(d[3])
        : "r"(a[0]), "r"(a[1]), "r"(a[2]), "r"(a[3]), "r"(b[0]), "r"(b[1]));
}

// ---------------------------------------------------------------------------
// HMMA GEMM (unchanged from R3): C = A * W^T (+bias), 2-way bf16 split,
// 3 products. CTA tile 128x128, BK=32, 8 warps.
// ---------------------------------------------------------------------------
#define BK          32
#define ROWB        80
#define TILEB       (128 * ROWB)
#define STAGEB      (4 * TILEB)
#define GEMM_SMEM   (2 * STAGEB)

__device__ __forceinline__ void split_store(char* smem, uint32_t off_hi,
                                            uint32_t off_lo, float4 v) {
    float in[4] = {v.x, v.y, v.z, v.w};
    __nv_bfloat16 hi[4], lo[4];
#pragma unroll
    for (int i = 0; i < 4; i++) {
        hi[i] = __float2bfloat16_rn(in[i]);
        lo[i] = __float2bfloat16_rn(in[i] - __bfloat162float(hi[i]));
    }
    __nv_bfloat162 h0 = __halves2bfloat162(hi[0], hi[1]);
    __nv_bfloat162 h1 = __halves2bfloat162(hi[2], hi[3]);
    __nv_bfloat162 l0 = __halves2bfloat162(lo[0], lo[1]);
    __nv_bfloat162 l1 = __halves2bfloat162(lo[2], lo[3]);
    *(uint2*)(smem + off_hi) = make_uint2(
        *reinterpret_cast<uint32_t*>(&h0), *reinterpret_cast<uint32_t*>(&h1));
    *(uint2*)(smem + off_lo) = make_uint2(
        *reinterpret_cast<uint32_t*>(&l0), *reinterpret_cast<uint32_t*>(&l1));
}

template<bool HAS_BIAS>
__global__ __launch_bounds__(256, 1)
void gemm_hmma(const float* __restrict__ A, const float* __restrict__ W,
               const float* __restrict__ bias, float* __restrict__ C)
{
    extern __shared__ char smem[];
    const uint32_t sb = smem_u32(smem);
    const int tid  = threadIdx.x;
    const int wid  = tid >> 5;
    const int lane = tid & 31;
    const int row0 = blockIdx.y * 128;
    const int col0 = blockIdx.x * 128;
    const int warp_m = (wid & 3) * 32;
    const int warp_n = (wid >> 2) * 64;

    const float* ag = A + (size_t)row0 * EDIM;
    const float* bg = W + (size_t)col0 * EDIM;

    const uint32_t a_loff = (uint32_t)(lane & 15) * ROWB + ((lane & 16) ? 16u : 0u);
    const uint32_t b_loff = (uint32_t)((lane & 7) + ((lane & 16) ? 8 : 0)) * ROWB
                          + ((lane & 8) ? 16u : 0u);

    float4 fa[4], fb[4];
#pragma unroll
    for (int it = 0; it < 4; it++) {
        int c = tid + it * 256;
        fa[it] = *(const float4*)(ag + (size_t)(c >> 3) * EDIM + (c & 7) * 4);
        fb[it] = *(const float4*)(bg + (size_t)(c >> 3) * EDIM + (c & 7) * 4);
    }
#pragma unroll
    for (int it = 0; it < 4; it++) {
        int c = tid + it * 256;
        uint32_t off = (uint32_t)(c >> 3) * ROWB + (uint32_t)(c & 7) * 8;
        split_store(smem, off, off + TILEB, fa[it]);
        split_store(smem, off + 2 * TILEB, off + 3 * TILEB, fb[it]);
    }
    __syncthreads();

    float acc[2][8][4];
#pragma unroll
    for (int mt = 0; mt < 2; mt++)
#pragma unroll
        for (int nt = 0; nt < 8; nt++)
#pragma unroll
            for (int i = 0; i < 4; i++) acc[mt][nt][i] = 0.f;

    const int NKT = EDIM / BK;
    for (int kt = 1; kt <= NKT; kt++) {
        if (kt < NKT) {
#pragma unroll
            for (int it = 0; it < 4; it++) {
                int c = tid + it * 256;
                fa[it] = *(const float4*)(ag + (size_t)(c >> 3) * EDIM + kt * BK + (c & 7) * 4);
                fb[it] = *(const float4*)(bg + (size_t)(c >> 3) * EDIM + kt * BK + (c & 7) * 4);
            }
        }

        const uint32_t base = sb + (uint32_t)((kt - 1) & 1) * STAGEB;
#pragma unroll
        for (int ks = 0; ks < 2; ks++) {
            const uint32_t koff = ks * 32;
            uint32_t afr[2][2][4];
#pragma unroll
            for (int sp = 0; sp < 2; sp++)
#pragma unroll
                for (int mt = 0; mt < 2; mt++)
                    ldsm_x4(afr[sp][mt],
                            base + sp * TILEB + (uint32_t)(warp_m + mt * 16) * ROWB
                                 + koff + a_loff);
            uint32_t bfr[2][4][4];
#pragma unroll
            for (int sp = 0; sp < 2; sp++)
#pragma unroll
                for (int np = 0; np < 4; np++)
                    ldsm_x4(bfr[sp][np],
                            base + (2 + sp) * TILEB + (uint32_t)(warp_n + np * 16) * ROWB
                                 + koff + b_loff);
#pragma unroll
            for (int mt = 0; mt < 2; mt++)
#pragma unroll
                for (int np = 0; np < 4; np++) {
                    mma16816(acc[mt][2 * np + 0], afr[0][mt], &bfr[0][np][0]);
                    mma16816(acc[mt][2 * np + 1], afr[0][mt], &bfr[0][np][2]);
                    mma16816(acc[mt][2 * np + 0], afr[0][mt], &bfr[1][np][0]);
                    mma16816(acc[mt][2 * np + 1], afr[0][mt], &bfr[1][np][2]);
                    mma16816(acc[mt][2 * np + 0], afr[1][mt], &bfr[0][np][0]);
                    mma16816(acc[mt][2 * np + 1], afr[1][mt], &bfr[0][np][2]);
                }
        }

        if (kt < NKT) {
            const uint32_t dst = (uint32_t)(kt & 1) * STAGEB;
#pragma unroll
            for (int it = 0; it < 4; it++) {
                int c = tid + it * 256;
                uint32_t off = dst + (uint32_t)(c >> 3) * ROWB + (uint32_t)(c & 7) * 8;
                split_store(smem, off, off + TILEB, fa[it]);
                split_store(smem, off + 2 * TILEB, off + 3 * TILEB, fb[it]);
            }
            __syncthreads();
        }
    }

    const int g   = lane >> 2;
    const int tig = lane & 3;
#pragma unroll
    for (int mt = 0; mt < 2; mt++) {
        int r = row0 + warp_m + mt * 16 + g;
#pragma unroll
        for (int nt = 0; nt < 8; nt++) {
            int col = col0 + warp_n + nt * 8 + 2 * tig;
            float bx = 0.f, by = 0.f;
            if (HAS_BIAS) { bx = bias[col]; by = bias[col + 1]; }
            *(float2*)(C + (size_t)r * EDIM + col) =
                make_float2(acc[mt][nt][0] + bx, acc[mt][nt][1] + by);
            *(float2*)(C + (size_t)(r + 8) * EDIM + col) =
                make_float2(acc[mt][nt][2] + bx, acc[mt][nt][3] + by);
        }
    }
}

// ---------------------------------------------------------------------------
// Flash attention on HMMA. Softmax over UNSCALED scores (faithful to the
// reference bug), single-pass without running max (scores bounded; exact by
// shift invariance). Br=128 (CTA), Bc=128/iter, D=64. 8 warps x 16 q-rows.
// K and V both stored [row][d/n] with identical layout; V's PV B-fragments
// come from ldmatrix.trans (no scalar scatter stores). 2-way bf16 split,
// 3 products for both GEMMs. P stays in registers.
// Smem: Khi | Klo | Vhi | Vlo, each 128 x (64 bf16 + pad) = 18432 B.
// ---------------------------------------------------------------------------
#define KROWB  144
#define KTILE  (128 * KROWB)             // 18432
#define FA2_SMEM (4 * KTILE)             // 73728

__global__ __launch_bounds__(256, 1)
void flash_hmma(const float* __restrict__ q, const float* __restrict__ k,
                const float* __restrict__ v, float* __restrict__ o)
{
    extern __shared__ char sm[];
    const uint32_t sb = smem_u32(sm);
    const int tid  = threadIdx.x;
    const int wid  = tid >> 5;
    const int lane = tid & 31;
    const int lr   = tid >> 1;        // loader row 0..127
    const int half = tid & 1;         // loader d-half
    const int warp_m = wid * 16;

    const int qt = blockIdx.x;
    const int h  = blockIdx.y;
    const int b  = blockIdx.z;
    const size_t baseRow = (size_t)b * SEQ;
    const int hcol = h * HD;

    const uint32_t a_loff  = (uint32_t)(lane & 15) * KROWB + ((lane & 16) ? 16u : 0u);
    const uint32_t bk_loff = (uint32_t)((lane & 7) + ((lane & 16) ? 8 : 0)) * KROWB
                           + ((lane & 8) ? 16u : 0u);
    // trans-ldsm lane offset: mat0=k0-7/n0-7, mat1=k8-15/n0-7, mat2=k0-7/n8-15, mat3=k8-15/n8-15
    const uint32_t bv_loff = (uint32_t)((lane & 7) + ((lane & 8) ? 8 : 0)) * KROWB
                           + ((lane & 16) ? 16u : 0u);

    // ---- stage Q through the K smem area, pull A-fragments to registers ----
    uint32_t qfr[2][4][4];   // [split][kstep][frag]
    {
        const float* qp = q + (baseRow + qt * 128 + lr) * EDIM + hcol + half * 32;
#pragma unroll
        for (int cc = 0; cc < 8; cc++) {
            float4 t = *(const float4*)(qp + cc * 4);
            uint32_t off = (uint32_t)lr * KROWB + (uint32_t)(half * 32 + cc * 4) * 2;
            split_store(sm, off, off + KTILE, t);
        }
        __syncthreads();
#pragma unroll
        for (int sp = 0; sp < 2; sp++)
#pragma unroll
            for (int ks = 0; ks < 4; ks++)
                ldsm_x4(qfr[sp][ks],
                        sb + sp * KTILE + (uint32_t)warp_m * KROWB + ks * 32 + a_loff);
    }

    float Oa[8][4];
#pragma unroll
    for (int i = 0; i < 8; i++)
#pragma unroll
        for (int c = 0; c < 4; c++) Oa[i][c] = 0.f;
    float l0 = 0.f, l1 = 0.f;

    for (int t = 0; t < SEQ / 128; t++) {
        // prefetch K/V tile to registers
        float4 kf[8], vf[8];
        {
            const float* kp = k + (baseRow + t * 128 + lr) * EDIM + hcol + half * 32;
            const float* vp = v + (baseRow + t * 128 + lr) * EDIM + hcol + half * 32;
#pragma unroll
            for (int cc = 0; cc < 8; cc++) {
                kf[cc] = *(const float4*)(kp + cc * 4);
                vf[cc] = *(const float4*)(vp + cc * 4);
            }
        }
        __syncthreads();   // previous iteration's ldsm done (Q frags at t=0)

        // K and V split stores: identical vectorized layout [row][d]
#pragma unroll
        for (int cc = 0; cc < 8; cc++) {
            uint32_t off = (uint32_t)lr * KROWB + (uint32_t)(half * 32 + cc * 4) * 2;
            split_store(sm, off, off + KTILE, kf[cc]);
            split_store(sm, 2 * KTILE + off, 3 * KTILE + off, vf[cc]);
        }
        __syncthreads();

        // ---- S = Q K^T : warp computes 16 x 128 ----
        // ks-outer / ng-inner: 8 independent accumulator pairs interleave.
        float S[8][2][4];
#pragma unroll
        for (int ng = 0; ng < 8; ng++)
#pragma unroll
            for (int tt = 0; tt < 2; tt++)
#pragma unroll
                for (int c = 0; c < 4; c++) S[ng][tt][c] = 0.f;

#pragma unroll
        for (int ks = 0; ks < 4; ks++) {
#pragma unroll
            for (int ng = 0; ng < 8; ng++) {
                uint32_t b1[4], b2[4];
                ldsm_x4(b1, sb + (uint32_t)(ng * 16) * KROWB + ks * 32 + bk_loff);
                ldsm_x4(b2, sb + KTILE + (uint32_t)(ng * 16) * KROWB + ks * 32 + bk_loff);
                mma16816(S[ng][0], qfr[0][ks], &b1[0]);
                mma16816(S[ng][1], qfr[0][ks], &b1[2]);
                mma16816(S[ng][0], qfr[0][ks], &b2[0]);
                mma16816(S[ng][1], qfr[0][ks], &b2[2]);
                mma16816(S[ng][0], qfr[1][ks], &b1[0]);
                mma16816(S[ng][1], qfr[1][ks], &b1[2]);
            }
        }

        // ---- exp (no max shift) + row sums ----
        float rs0 = 0.f, rs1 = 0.f;
#pragma unroll
        for (int ng = 0; ng < 8; ng++)
#pragma unroll
            for (int tt = 0; tt < 2; tt++) {
                S[ng][tt][0] = __expf(S[ng][tt][0]);
                S[ng][tt][1] = __expf(S[ng][tt][1]);
                S[ng][tt][2] = __expf(S[ng][tt][2]);
                S[ng][tt][3] = __expf(S[ng][tt][3]);
                rs0 += S[ng][tt][0] + S[ng][tt][1];
                rs1 += S[ng][tt][2] + S[ng][tt][3];
            }
        rs0 += __shfl_xor_sync(0xffffffffu, rs0, 1);
        rs0 += __shfl_xor_sync(0xffffffffu, rs0, 2);
        rs1 += __shfl_xor_sync(0xffffffffu, rs1, 1);
        rs1 += __shfl_xor_sync(0xffffffffu, rs1, 2);
        l0 += rs0;
        l1 += rs1;

        // ---- O += P V : P split in registers, V B-fragments via ldsm.trans ----
#pragma unroll
        for (int kk = 0; kk < 8; kk++) {
            uint32_t p1[4], p2[4];
#pragma unroll
            for (int tt = 0; tt < 2; tt++) {
#pragma unroll
                for (int hl = 0; hl < 2; hl++) {
                    float x = S[kk][tt][2 * hl + 0];
                    float y = S[kk][tt][2 * hl + 1];
                    __nv_bfloat16 hx = __float2bfloat16_rn(x);
                    __nv_bfloat16 hy = __float2bfloat16_rn(y);
                    __nv_bfloat162 hp = __halves2bfloat162(hx, hy);
                    p1[tt * 2 + hl] = *reinterpret_cast<uint32_t*>(&hp);
                    __nv_bfloat162 lp = __halves2bfloat162(
                        __float2bfloat16_rn(x - __bfloat162float(hx)),
                        __float2bfloat16_rn(y - __bfloat162float(hy)));
                    p2[tt * 2 + hl] = *reinterpret_cast<uint32_t*>(&lp);
                }
            }
#pragma unroll
            for (int dg = 0; dg < 4; dg++) {
                uint32_t v1[4], v2[4];
                uint32_t vb = sb + 2 * KTILE + (uint32_t)(kk * 16) * KROWB + dg * 32 + bv_loff;
                ldsm_x4_t(v1, vb);
                ldsm_x4_t(v2, vb + KTILE);
                mma16816(Oa[dg * 2 + 0], p1, &v1[0]);
                mma16816(Oa[dg * 2 + 1], p1, &v1[2]);
                mma16816(Oa[dg * 2 + 0], p1, &v2[0]);
                mma16816(Oa[dg * 2 + 1], p1, &v2[2]);
                mma16816(Oa[dg * 2 + 0], p2, &v1[0]);
                mma16816(Oa[dg * 2 + 1], p2, &v1[2]);
            }
        }
    }

    // ---- normalize & write ----
    const int g   = lane >> 2;
    const int tq2 = (lane & 3) * 2;
    const float inv0 = 1.0f / l0;
    const float inv1 = 1.0f / l1;
    float* op0 = o + (baseRow + qt * 128 + warp_m + g) * EDIM + hcol;
    float* op1 = op0 + (size_t)8 * EDIM;
#pragma unroll
    for (int i = 0; i < 8; i++) {
        int d = i * 8 + tq2;
        *(float2*)(op0 + d) = make_float2(Oa[i][0] * inv0, Oa[i][1] * inv0);
        *(float2*)(op1 + d) = make_float2(Oa[i][2] * inv1, Oa[i][3] * inv1);
    }
}

// ---------------------------------------------------------------------------
extern "C" void kernel_launch(void* const* d_in, const int* in_sizes, int n_in,
                              void* d_out, int out_size)
{
    (void)in_sizes; (void)n_in; (void)out_size;

    const float* Q  = (const float*)d_in[0];
    const float* K  = (const float*)d_in[1];
    const float* V  = (const float*)d_in[2];
    const float* Wq = (const float*)d_in[3];
    const float* Wk = (const float*)d_in[4];
    const float* Wv = (const float*)d_in[5];
    const float* Wo = (const float*)d_in[6];
    const float* bo = (const float*)d_in[7];
    float* out = (float*)d_out;

    float *gq, *gk, *gv, *go;
    cudaGetSymbolAddress((void**)&gq, g_q);
    cudaGetSymbolAddress((void**)&gk, g_k);
    cudaGetSymbolAddress((void**)&gv, g_v);
    cudaGetSymbolAddress((void**)&go, g_o);

    cudaFuncSetAttribute(gemm_hmma<false>,
                         cudaFuncAttributeMaxDynamicSharedMemorySize, GEMM_SMEM);
    cudaFuncSetAttribute(gemm_hmma<true>,
                         cudaFuncAttributeMaxDynamicSharedMemorySize, GEMM_SMEM);
    cudaFuncSetAttribute(flash_hmma,
                         cudaFuncAttributeMaxDynamicSharedMemorySize, FA2_SMEM);

    dim3 gemmGrid(EDIM / 128, MTOT / 128);

    gemm_hmma<false><<<gemmGrid, 256, GEMM_SMEM>>>(Q, Wq, nullptr, gq);
    gemm_hmma<false><<<gemmGrid, 256, GEMM_SMEM>>>(K, Wk, nullptr, gk);
    gemm_hmma<false><<<gemmGrid, 256, GEMM_SMEM>>>(V, Wv, nullptr, gv);

    flash_hmma<<<dim3(SEQ / 128, NH, NB), 256, FA2_SMEM>>>(gq, gk, gv, go);

    gemm_hmma<true><<<gemmGrid, 256, GEMM_SMEM>>>(go, Wo, bo, out);
}

// round 6
// speedup vs baseline: 2.4393x; 1.1082x over previous
#include <cuda_runtime.h>
#include <cuda_bf16.h>
#include <cstdint>

#define EDIM 1024
#define NH   16
#define HD   64
#define NB   4
#define SEQ  2048
#define MTOT (NB*SEQ)   // 8192 rows

// ---------------------------------------------------------------------------
// Scratch (device globals). All bf16 split pairs, row-major [*, 1024].
// ---------------------------------------------------------------------------
__device__ __nv_bfloat16 g_ah[(size_t)MTOT * EDIM];   // generic GEMM A hi
__device__ __nv_bfloat16 g_al[(size_t)MTOT * EDIM];   // generic GEMM A lo
__device__ __nv_bfloat16 g_wh[(size_t)EDIM * EDIM];
__device__ __nv_bfloat16 g_wl[(size_t)EDIM * EDIM];
__device__ __nv_bfloat16 g_qh[(size_t)MTOT * EDIM];
__device__ __nv_bfloat16 g_ql[(size_t)MTOT * EDIM];
__device__ __nv_bfloat16 g_kh[(size_t)MTOT * EDIM];
__device__ __nv_bfloat16 g_kl[(size_t)MTOT * EDIM];
__device__ __nv_bfloat16 g_vh[(size_t)MTOT * EDIM];
__device__ __nv_bfloat16 g_vl[(size_t)MTOT * EDIM];

// ---------------------------------------------------------------------------
// helpers
// ---------------------------------------------------------------------------
__device__ __forceinline__ uint32_t smem_u32(const void* p) {
    uint32_t a;
    asm("{ .reg .u64 t; cvta.to.shared.u64 t, %1; cvt.u32.u64 %0, t; }"
        : "=r"(a) : "l"(p));
    return a;
}

__device__ __forceinline__ void ldsm_x4(uint32_t* r, uint32_t addr) {
    asm volatile("ldmatrix.sync.aligned.m8n8.x4.shared.b16 {%0,%1,%2,%3}, [%4];"
                 : "=r"(r[0]), "=r"(r[1]), "=r"(r[2]), "=r"(r[3]) : "r"(addr));
}

__device__ __forceinline__ void ldsm_x4_t(uint32_t* r, uint32_t addr) {
    asm volatile("ldmatrix.sync.aligned.m8n8.x4.trans.shared.b16 {%0,%1,%2,%3}, [%4];"
                 : "=r"(r[0]), "=r"(r[1]), "=r"(r[2]), "=r"(r[3]) : "r"(addr));
}

__device__ __forceinline__ void mma16816(float* d, const uint32_t* a,
                                         const uint32_t* b) {
    asm volatile(
        "mma.sync.aligned.m16n8k16.row.col.f32.bf16.bf16.f32 "
        "{%0,%1,%2,%3}, {%4,%5,%6,%7}, {%8,%9}, {%0,%1,%2,%3};"
        : "+f"(d[0]), "+f"(d[1]), "+f"(d[2]), "+f"(d[3])
        : "r"(a[0]), "r"(a[1]), "r"(a[2]), "r"(a[3]), "r"(b[0]), "r"(b[1]));
}

__device__ __forceinline__ void cp16(uint32_t smem_dst, const void* gptr) {
    asm volatile("cp.async.cg.shared.global [%0], [%1], 16;"
                 :: "r"(smem_dst), "l"(gptr));
}
#define CP_COMMIT() asm volatile("cp.async.commit_group;")
#define CP_WAIT(n)  asm volatile("cp.async.wait_group %0;" :: "n"(n))

// split a float pair into hi/lo bf16x2 words
__device__ __forceinline__ void split_pair(float x, float y,
                                           uint32_t& hi, uint32_t& lo) {
    __nv_bfloat16 hx = __float2bfloat16_rn(x);
    __nv_bfloat16 hy = __float2bfloat16_rn(y);
    __nv_bfloat162 h2 = __halves2bfloat162(hx, hy);
    __nv_bfloat162 l2 = __halves2bfloat162(
        __float2bfloat16_rn(x - __bfloat162float(hx)),
        __float2bfloat16_rn(y - __bfloat162float(hy)));
    hi = *reinterpret_cast<uint32_t*>(&h2);
    lo = *reinterpret_cast<uint32_t*>(&l2);
}

// ---------------------------------------------------------------------------
// fp32 -> (hi, lo) bf16 split pass
// ---------------------------------------------------------------------------
__global__ void split2_kernel(const float* __restrict__ x,
                              __nv_bfloat16* __restrict__ oh,
                              __nv_bfloat16* __restrict__ ol, int n4)
{
    int i = blockIdx.x * blockDim.x + threadIdx.x;
    if (i >= n4) return;
    float4 v = reinterpret_cast<const float4*>(x)[i];
    uint32_t h0, l0, h1, l1;
    split_pair(v.x, v.y, h0, l0);
    split_pair(v.z, v.w, h1, l1);
    reinterpret_cast<uint2*>(oh)[i] = make_uint2(h0, h1);
    reinterpret_cast<uint2*>(ol)[i] = make_uint2(l0, l1);
}

// ---------------------------------------------------------------------------
// HMMA GEMM on pre-split bf16 inputs: C = A * W^T, 3 products
// (AhWh + AhWl + AlWh). CTA tile 128x128, BK=32, 8 warps, cp.async
// 3-stage pipeline. Output: either split bf16 pair or fp32 (+bias).
// ---------------------------------------------------------------------------
#define ROWB        80                   // 32 bf16 + 16B pad
#define TILEB       (128 * ROWB)         // 10240
#define STAGEB      (4 * TILEB)          // 40960
#define GEMM_SMEM   (3 * STAGEB)         // 122880

template<bool SPLIT_OUT>
__global__ __launch_bounds__(256, 1)
void gemm_hmma(const __nv_bfloat16* __restrict__ Ah, const __nv_bfloat16* __restrict__ Al,
               const __nv_bfloat16* __restrict__ Wh, const __nv_bfloat16* __restrict__ Wl,
               const float* __restrict__ bias,
               float* __restrict__ C,
               __nv_bfloat16* __restrict__ Ch, __nv_bfloat16* __restrict__ Cl)
{
    extern __shared__ char smem[];
    const uint32_t sb = smem_u32(smem);
    const int tid  = threadIdx.x;
    const int wid  = tid >> 5;
    const int lane = tid & 31;
    const int row0 = blockIdx.y * 128;
    const int col0 = blockIdx.x * 128;
    const int warp_m = (wid & 3) * 32;
    const int warp_n = (wid >> 2) * 64;

    const uint32_t a_loff = (uint32_t)(lane & 15) * ROWB + ((lane & 16) ? 16u : 0u);
    const uint32_t b_loff = (uint32_t)((lane & 7) + ((lane & 16) ? 8 : 0)) * ROWB
                          + ((lane & 8) ? 16u : 0u);

    // cp.async loader: per tile 2 chunks/thread (128 rows x 4 x 16B = 512)
    const int lrow = tid >> 2;           // for chunk c = tid*? -> use c = tid + it*256
    (void)lrow;

    auto issue_stage = [&](int s, int buf) {
        const uint32_t base = sb + (uint32_t)buf * STAGEB;
#pragma unroll
        for (int it = 0; it < 2; it++) {
            int c = tid + it * 256;            // 0..511
            int row = c >> 2, c16 = c & 3;
            uint32_t doff = (uint32_t)row * ROWB + (uint32_t)c16 * 16;
            size_t ga = (size_t)(row0 + row) * EDIM + s * 32 + c16 * 8;
            size_t gw = (size_t)(col0 + row) * EDIM + s * 32 + c16 * 8;
            cp16(base + doff,             Ah + ga);
            cp16(base + TILEB + doff,     Al + ga);
            cp16(base + 2 * TILEB + doff, Wh + gw);
            cp16(base + 3 * TILEB + doff, Wl + gw);
        }
        CP_COMMIT();
    };

    issue_stage(0, 0);
    issue_stage(1, 1);

    float acc[2][8][4];
#pragma unroll
    for (int mt = 0; mt < 2; mt++)
#pragma unroll
        for (int nt = 0; nt < 8; nt++)
#pragma unroll
            for (int i = 0; i < 4; i++) acc[mt][nt][i] = 0.f;

    const int NKT = EDIM / 32;   // 32
    for (int s = 0; s < NKT; s++) {
        if (s + 1 < NKT) { CP_WAIT(1); } else { CP_WAIT(0); }
        __syncthreads();

        const uint32_t base = sb + (uint32_t)(s % 3) * STAGEB;
#pragma unroll
        for (int ks = 0; ks < 2; ks++) {
            const uint32_t koff = ks * 32;
            uint32_t afr[2][2][4];
#pragma unroll
            for (int sp = 0; sp < 2; sp++)
#pragma unroll
                for (int mt = 0; mt < 2; mt++)
                    ldsm_x4(afr[sp][mt],
                            base + sp * TILEB + (uint32_t)(warp_m + mt * 16) * ROWB
                                 + koff + a_loff);
            uint32_t bfr[2][4][4];
#pragma unroll
            for (int sp = 0; sp < 2; sp++)
#pragma unroll
                for (int np = 0; np < 4; np++)
                    ldsm_x4(bfr[sp][np],
                            base + (2 + sp) * TILEB + (uint32_t)(warp_n + np * 16) * ROWB
                                 + koff + b_loff);
#pragma unroll
            for (int mt = 0; mt < 2; mt++)
#pragma unroll
                for (int np = 0; np < 4; np++) {
                    mma16816(acc[mt][2 * np + 0], afr[0][mt], &bfr[0][np][0]);
                    mma16816(acc[mt][2 * np + 1], afr[0][mt], &bfr[0][np][2]);
                    mma16816(acc[mt][2 * np + 0], afr[0][mt], &bfr[1][np][0]);
                    mma16816(acc[mt][2 * np + 1], afr[0][mt], &bfr[1][np][2]);
                    mma16816(acc[mt][2 * np + 0], afr[1][mt], &bfr[0][np][0]);
                    mma16816(acc[mt][2 * np + 1], afr[1][mt], &bfr[0][np][2]);
                }
        }

        __syncthreads();
        if (s + 2 < NKT) issue_stage(s + 2, (s + 2) % 3);
    }

    const int g   = lane >> 2;
    const int tig = lane & 3;
#pragma unroll
    for (int mt = 0; mt < 2; mt++) {
        int r = row0 + warp_m + mt * 16 + g;
#pragma unroll
        for (int nt = 0; nt < 8; nt++) {
            int col = col0 + warp_n + nt * 8 + 2 * tig;
            if (SPLIT_OUT) {
                uint32_t h, l;
                split_pair(acc[mt][nt][0], acc[mt][nt][1], h, l);
                *(uint32_t*)(Ch + (size_t)r * EDIM + col) = h;
                *(uint32_t*)(Cl + (size_t)r * EDIM + col) = l;
                split_pair(acc[mt][nt][2], acc[mt][nt][3], h, l);
                *(uint32_t*)(Ch + (size_t)(r + 8) * EDIM + col) = h;
                *(uint32_t*)(Cl + (size_t)(r + 8) * EDIM + col) = l;
            } else {
                float bx = bias[col], by = bias[col + 1];
                *(float2*)(C + (size_t)r * EDIM + col) =
                    make_float2(acc[mt][nt][0] + bx, acc[mt][nt][1] + by);
                *(float2*)(C + (size_t)(r + 8) * EDIM + col) =
                    make_float2(acc[mt][nt][2] + bx, acc[mt][nt][3] + by);
            }
        }
    }
}

// ---------------------------------------------------------------------------
// Flash attention on HMMA, pre-split bf16 inputs via cp.async double-buffer.
// Softmax over UNSCALED scores (faithful to the reference bug), single pass,
// no running max (bounded scores; shift-invariance makes this exact).
// Br=128 (CTA), Bc=128/iter, D=64, 8 warps x 16 q-rows.
// Output written as split bf16 pair (input to the Wo GEMM).
// Smem/stage: Khi|Klo|Vhi|Vlo, each 128 x (64 bf16 + 16B pad) = 18432 B.
// ---------------------------------------------------------------------------
#define KROWB  144
#define KTILE  (128 * KROWB)                 // 18432
#define FA_STAGE (4 * KTILE)                 // 73728
#define FA_SMEM  (2 * FA_STAGE)              // 147456

__global__ __launch_bounds__(256, 1)
void flash_hmma(const __nv_bfloat16* __restrict__ qh, const __nv_bfloat16* __restrict__ ql,
                const __nv_bfloat16* __restrict__ kh, const __nv_bfloat16* __restrict__ kl,
                const __nv_bfloat16* __restrict__ vh, const __nv_bfloat16* __restrict__ vl,
                __nv_bfloat16* __restrict__ oh, __nv_bfloat16* __restrict__ ol)
{
    extern __shared__ char sm[];
    const uint32_t sb = smem_u32(sm);
    const int tid  = threadIdx.x;
    const int wid  = tid >> 5;
    const int lane = tid & 31;
    const int warp_m = wid * 16;

    const int qt = blockIdx.x;
    const int h  = blockIdx.y;
    const int b  = blockIdx.z;
    const size_t baseRow = (size_t)b * SEQ;
    const int hcol = h * HD;

    const uint32_t a_loff  = (uint32_t)(lane & 15) * KROWB + ((lane & 16) ? 16u : 0u);
    const uint32_t bk_loff = (uint32_t)((lane & 7) + ((lane & 16) ? 8 : 0)) * KROWB
                           + ((lane & 8) ? 16u : 0u);
    const uint32_t bv_loff = (uint32_t)((lane & 7) + ((lane & 8) ? 8 : 0)) * KROWB
                           + ((lane & 16) ? 16u : 0u);

    // per-thread cp.async chunks: tile = 128 rows x 8 x 16B = 1024 chunks; 4/thread
    // ---- stage Q into buffer 0, pull A-fragments ----
    {
#pragma unroll
        for (int it = 0; it < 4; it++) {
            int c = tid + it * 256;
            int row = c >> 3, ch = c & 7;
            uint32_t doff = (uint32_t)row * KROWB + (uint32_t)ch * 16;
            size_t ga = (baseRow + qt * 128 + row) * EDIM + hcol + ch * 8;
            cp16(sb + doff,         qh + ga);
            cp16(sb + KTILE + doff, ql + ga);
        }
        CP_COMMIT();
        CP_WAIT(0);
        __syncthreads();
    }
    uint32_t qfr[2][4][4];
#pragma unroll
    for (int sp = 0; sp < 2; sp++)
#pragma unroll
        for (int ks = 0; ks < 4; ks++)
            ldsm_x4(qfr[sp][ks],
                    sb + sp * KTILE + (uint32_t)warp_m * KROWB + ks * 32 + a_loff);
    __syncthreads();   // everyone done reading Q before K/V overwrite

    auto issue_kv = [&](int t, int buf) {
        const uint32_t base = sb + (uint32_t)buf * FA_STAGE;
#pragma unroll
        for (int it = 0; it < 4; it++) {
            int c = tid + it * 256;
            int row = c >> 3, ch = c & 7;
            uint32_t doff = (uint32_t)row * KROWB + (uint32_t)ch * 16;
            size_t ga = (baseRow + t * 128 + row) * EDIM + hcol + ch * 8;
            cp16(base + doff,             kh + ga);
            cp16(base + KTILE + doff,     kl + ga);
            cp16(base + 2 * KTILE + doff, vh + ga);
            cp16(base + 3 * KTILE + doff, vl + ga);
        }
        CP_COMMIT();
    };

    issue_kv(0, 0);
    issue_kv(1, 1);

    float Oa[8][4];
#pragma unroll
    for (int i = 0; i < 8; i++)
#pragma unroll
        for (int c = 0; c < 4; c++) Oa[i][c] = 0.f;
    float l0 = 0.f, l1 = 0.f;

    const int NT = SEQ / 128;   // 16
    for (int t = 0; t < NT; t++) {
        if (t + 1 < NT) { CP_WAIT(1); } else { CP_WAIT(0); }
        __syncthreads();

        const uint32_t bs = sb + (uint32_t)(t & 1) * FA_STAGE;

        // ---- S = Q K^T ----
        float S[8][2][4];
#pragma unroll
        for (int ng = 0; ng < 8; ng++)
#pragma unroll
            for (int tt = 0; tt < 2; tt++)
#pragma unroll
                for (int c = 0; c < 4; c++) S[ng][tt][c] = 0.f;

#pragma unroll
        for (int ks = 0; ks < 4; ks++) {
#pragma unroll
            for (int ng = 0; ng < 8; ng++) {
                uint32_t b1[4], b2[4];
                ldsm_x4(b1, bs + (uint32_t)(ng * 16) * KROWB + ks * 32 + bk_loff);
                ldsm_x4(b2, bs + KTILE + (uint32_t)(ng * 16) * KROWB + ks * 32 + bk_loff);
                mma16816(S[ng][0], qfr[0][ks], &b1[0]);
                mma16816(S[ng][1], qfr[0][ks], &b1[2]);
                mma16816(S[ng][0], qfr[0][ks], &b2[0]);
                mma16816(S[ng][1], qfr[0][ks], &b2[2]);
                mma16816(S[ng][0], qfr[1][ks], &b1[0]);
                mma16816(S[ng][1], qfr[1][ks], &b1[2]);
            }
        }

        // ---- exp + row sums ----
        float rs0 = 0.f, rs1 = 0.f;
#pragma unroll
        for (int ng = 0; ng < 8; ng++)
#pragma unroll
            for (int tt = 0; tt < 2; tt++) {
                S[ng][tt][0] = __expf(S[ng][tt][0]);
                S[ng][tt][1] = __expf(S[ng][tt][1]);
                S[ng][tt][2] = __expf(S[ng][tt][2]);
                S[ng][tt][3] = __expf(S[ng][tt][3]);
                rs0 += S[ng][tt][0] + S[ng][tt][1];
                rs1 += S[ng][tt][2] + S[ng][tt][3];
            }
        rs0 += __shfl_xor_sync(0xffffffffu, rs0, 1);
        rs0 += __shfl_xor_sync(0xffffffffu, rs0, 2);
        rs1 += __shfl_xor_sync(0xffffffffu, rs1, 1);
        rs1 += __shfl_xor_sync(0xffffffffu, rs1, 2);
        l0 += rs0;
        l1 += rs1;

        // ---- O += P V ----
#pragma unroll
        for (int kk = 0; kk < 8; kk++) {
            uint32_t p1[4], p2[4];
#pragma unroll
            for (int tt = 0; tt < 2; tt++)
#pragma unroll
                for (int hl = 0; hl < 2; hl++)
                    split_pair(S[kk][tt][2 * hl + 0], S[kk][tt][2 * hl + 1],
                               p1[tt * 2 + hl], p2[tt * 2 + hl]);
#pragma unroll
            for (int dg = 0; dg < 4; dg++) {
                uint32_t v1[4], v2[4];
                uint32_t vb = bs + 2 * KTILE + (uint32_t)(kk * 16) * KROWB + dg * 32 + bv_loff;
                ldsm_x4_t(v1, vb);
                ldsm_x4_t(v2, vb + KTILE);
                mma16816(Oa[dg * 2 + 0], p1, &v1[0]);
                mma16816(Oa[dg * 2 + 1], p1, &v1[2]);
                mma16816(Oa[dg * 2 + 0], p1, &v2[0]);
                mma16816(Oa[dg * 2 + 1], p1, &v2[2]);
                mma16816(Oa[dg * 2 + 0], p2, &v1[0]);
                mma16816(Oa[dg * 2 + 1], p2, &v1[2]);
            }
        }

        __syncthreads();
        if (t + 2 < NT) issue_kv(t + 2, t & 1);
    }

    // ---- normalize & write split output ----
    const int g   = lane >> 2;
    const int tq2 = (lane & 3) * 2;
    const float inv0 = 1.0f / l0;
    const float inv1 = 1.0f / l1;
    const size_t r0 = (baseRow + qt * 128 + warp_m + g) * EDIM + hcol;
    const size_t r1 = r0 + (size_t)8 * EDIM;
#pragma unroll
    for (int i = 0; i < 8; i++) {
        int d = i * 8 + tq2;
        uint32_t h, l;
        split_pair(Oa[i][0] * inv0, Oa[i][1] * inv0, h, l);
        *(uint32_t*)(oh + r0 + d) = h;
        *(uint32_t*)(ol + r0 + d) = l;
        split_pair(Oa[i][2] * inv1, Oa[i][3] * inv1, h, l);
        *(uint32_t*)(oh + r1 + d) = h;
        *(uint32_t*)(ol + r1 + d) = l;
    }
}

// ---------------------------------------------------------------------------
extern "C" void kernel_launch(void* const* d_in, const int* in_sizes, int n_in,
                              void* d_out, int out_size)
{
    (void)in_sizes; (void)n_in; (void)out_size;

    const float* Q  = (const float*)d_in[0];
    const float* K  = (const float*)d_in[1];
    const float* V  = (const float*)d_in[2];
    const float* Wq = (const float*)d_in[3];
    const float* Wk = (const float*)d_in[4];
    const float* Wv = (const float*)d_in[5];
    const float* Wo = (const float*)d_in[6];
    const float* bo = (const float*)d_in[7];
    float* out = (float*)d_out;

    __nv_bfloat16 *ah, *al, *wh, *wl, *qh, *ql, *kh, *kl, *vh, *vl;
    cudaGetSymbolAddress((void**)&ah, g_ah);
    cudaGetSymbolAddress((void**)&al, g_al);
    cudaGetSymbolAddress((void**)&wh, g_wh);
    cudaGetSymbolAddress((void**)&wl, g_wl);
    cudaGetSymbolAddress((void**)&qh, g_qh);
    cudaGetSymbolAddress((void**)&ql, g_ql);
    cudaGetSymbolAddress((void**)&kh, g_kh);
    cudaGetSymbolAddress((void**)&kl, g_kl);
    cudaGetSymbolAddress((void**)&vh, g_vh);
    cudaGetSymbolAddress((void**)&vl, g_vl);

    cudaFuncSetAttribute(gemm_hmma<true>,
                         cudaFuncAttributeMaxDynamicSharedMemorySize, GEMM_SMEM);
    cudaFuncSetAttribute(gemm_hmma<false>,
                         cudaFuncAttributeMaxDynamicSharedMemorySize, GEMM_SMEM);
    cudaFuncSetAttribute(flash_hmma,
                         cudaFuncAttributeMaxDynamicSharedMemorySize, FA_SMEM);

    const int nA4 = MTOT * EDIM / 4;
    const int nW4 = EDIM * EDIM / 4;
    dim3 gemmGrid(EDIM / 128, MTOT / 128);

    // Q projection -> split output
    split2_kernel<<<nA4 / 256, 256>>>(Q, ah, al, nA4);
    split2_kernel<<<nW4 / 256, 256>>>(Wq, wh, wl, nW4);
    gemm_hmma<true><<<gemmGrid, 256, GEMM_SMEM>>>(ah, al, wh, wl, nullptr,
                                                  nullptr, qh, ql);
    // K projection
    split2_kernel<<<nA4 / 256, 256>>>(K, ah, al, nA4);
    split2_kernel<<<nW4 / 256, 256>>>(Wk, wh, wl, nW4);
    gemm_hmma<true><<<gemmGrid, 256, GEMM_SMEM>>>(ah, al, wh, wl, nullptr,
                                                  nullptr, kh, kl);
    // V projection
    split2_kernel<<<nA4 / 256, 256>>>(V, ah, al, nA4);
    split2_kernel<<<nW4 / 256, 256>>>(Wv, wh, wl, nW4);
    gemm_hmma<true><<<gemmGrid, 256, GEMM_SMEM>>>(ah, al, wh, wl, nullptr,
                                                  nullptr, vh, vl);

    // Attention, split output into (ah, al)
    flash_hmma<<<dim3(SEQ / 128, NH, NB), 256, FA_SMEM>>>(qh, ql, kh, kl,
                                                          vh, vl, ah, al);

    // Output projection (+bias), fp32 out
    split2_kernel<<<nW4 / 256, 256>>>(Wo, wh, wl, nW4);
    gemm_hmma<false><<<gemmGrid, 256, GEMM_SMEM>>>(ah, al, wh, wl, bo,
                                                   out, nullptr, nullptr);
}

// round 7
// speedup vs baseline: 2.7210x; 1.1155x over previous
#include <cuda_runtime.h>
#include <cuda_bf16.h>
#include <cstdint>

#define EDIM 1024
#define NH   16
#define HD   64
#define NB   4
#define SEQ  2048
#define MTOT (NB*SEQ)   // 8192 rows

// ---------------------------------------------------------------------------
// Scratch (device globals). All bf16 split pairs, row-major [*, 1024].
// ---------------------------------------------------------------------------
__device__ __nv_bfloat16 g_ah[(size_t)MTOT * EDIM];
__device__ __nv_bfloat16 g_al[(size_t)MTOT * EDIM];
__device__ __nv_bfloat16 g_wh[(size_t)EDIM * EDIM];
__device__ __nv_bfloat16 g_wl[(size_t)EDIM * EDIM];
__device__ __nv_bfloat16 g_qh[(size_t)MTOT * EDIM];
__device__ __nv_bfloat16 g_ql[(size_t)MTOT * EDIM];
__device__ __nv_bfloat16 g_kh[(size_t)MTOT * EDIM];
__device__ __nv_bfloat16 g_kl[(size_t)MTOT * EDIM];
__device__ __nv_bfloat16 g_vh[(size_t)MTOT * EDIM];
__device__ __nv_bfloat16 g_vl[(size_t)MTOT * EDIM];

// ---------------------------------------------------------------------------
// helpers
// ---------------------------------------------------------------------------
__device__ __forceinline__ uint32_t smem_u32(const void* p) {
    uint32_t a;
    asm("{ .reg .u64 t; cvta.to.shared.u64 t, %1; cvt.u32.u64 %0, t; }"
        : "=r"(a) : "l"(p));
    return a;
}

__device__ __forceinline__ void ldsm_x4(uint32_t* r, uint32_t addr) {
    asm volatile("ldmatrix.sync.aligned.m8n8.x4.shared.b16 {%0,%1,%2,%3}, [%4];"
                 : "=r"(r[0]), "=r"(r[1]), "=r"(r[2]), "=r"(r[3]) : "r"(addr));
}

__device__ __forceinline__ void ldsm_x4_t(uint32_t* r, uint32_t addr) {
    asm volatile("ldmatrix.sync.aligned.m8n8.x4.trans.shared.b16 {%0,%1,%2,%3}, [%4];"
                 : "=r"(r[0]), "=r"(r[1]), "=r"(r[2]), "=r"(r[3]) : "r"(addr));
}

__device__ __forceinline__ void mma16816(float* d, const uint32_t* a,
                                         const uint32_t* b) {
    asm volatile(
        "mma.sync.aligned.m16n8k16.row.col.f32.bf16.bf16.f32 "
        "{%0,%1,%2,%3}, {%4,%5,%6,%7}, {%8,%9}, {%0,%1,%2,%3};"
        : "+f"(d[0]), "+f"(d[1]), "+f"(d[2]), "+f"(d[3])
        : "r"(a[0]), "r"(a[1]), "r"(a[2]), "r"(a[3]), "r"(b[0]), "r"(b[1]));
}

__device__ __forceinline__ void cp16(uint32_t smem_dst, const void* gptr) {
    asm volatile("cp.async.cg.shared.global [%0], [%1], 16;"
                 :: "r"(smem_dst), "l"(gptr));
}
#define CP_COMMIT() asm volatile("cp.async.commit_group;")
#define CP_WAIT(n)  asm volatile("cp.async.wait_group %0;" :: "n"(n))

__device__ __forceinline__ void split_pair(float x, float y,
                                           uint32_t& hi, uint32_t& lo) {
    __nv_bfloat16 hx = __float2bfloat16_rn(x);
    __nv_bfloat16 hy = __float2bfloat16_rn(y);
    __nv_bfloat162 h2 = __halves2bfloat162(hx, hy);
    __nv_bfloat162 l2 = __halves2bfloat162(
        __float2bfloat16_rn(x - __bfloat162float(hx)),
        __float2bfloat16_rn(y - __bfloat162float(hy)));
    hi = *reinterpret_cast<uint32_t*>(&h2);
    lo = *reinterpret_cast<uint32_t*>(&l2);
}

// ---------------------------------------------------------------------------
// fp32 -> (hi, lo) bf16 split pass
// ---------------------------------------------------------------------------
__global__ void split2_kernel(const float* __restrict__ x,
                              __nv_bfloat16* __restrict__ oh,
                              __nv_bfloat16* __restrict__ ol, int n4)
{
    int i = blockIdx.x * blockDim.x + threadIdx.x;
    if (i >= n4) return;
    float4 v = reinterpret_cast<const float4*>(x)[i];
    uint32_t h0, l0, h1, l1;
    split_pair(v.x, v.y, h0, l0);
    split_pair(v.z, v.w, h1, l1);
    reinterpret_cast<uint2*>(oh)[i] = make_uint2(h0, h1);
    reinterpret_cast<uint2*>(ol)[i] = make_uint2(l0, l1);
}

// ---------------------------------------------------------------------------
// HMMA GEMM on pre-split bf16: C = A * W^T, 3 products.
// CTA tile 128x128, BK=32, 8 warps, 2-stage cp.async pipeline,
// 2 CTAs/SM (launch_bounds 256,2). B-fragments loaded per-np to cut
// register liveness.
// ---------------------------------------------------------------------------
#define ROWB        80                   // 32 bf16 + 16B pad
#define TILEB       (128 * ROWB)         // 10240
#define STAGEB      (4 * TILEB)          // 40960
#define GEMM_SMEM   (2 * STAGEB)         // 81920

template<bool SPLIT_OUT>
__global__ __launch_bounds__(256, 2)
void gemm_hmma(const __nv_bfloat16* __restrict__ Ah, const __nv_bfloat16* __restrict__ Al,
               const __nv_bfloat16* __restrict__ Wh, const __nv_bfloat16* __restrict__ Wl,
               const float* __restrict__ bias,
               float* __restrict__ C,
               __nv_bfloat16* __restrict__ Ch, __nv_bfloat16* __restrict__ Cl)
{
    extern __shared__ char smem[];
    const uint32_t sb = smem_u32(smem);
    const int tid  = threadIdx.x;
    const int wid  = tid >> 5;
    const int lane = tid & 31;
    const int row0 = blockIdx.y * 128;
    const int col0 = blockIdx.x * 128;
    const int warp_m = (wid & 3) * 32;
    const int warp_n = (wid >> 2) * 64;

    const uint32_t a_loff = (uint32_t)(lane & 15) * ROWB + ((lane & 16) ? 16u : 0u);
    const uint32_t b_loff = (uint32_t)((lane & 7) + ((lane & 16) ? 8 : 0)) * ROWB
                          + ((lane & 8) ? 16u : 0u);

    auto issue_stage = [&](int s, int buf) {
        const uint32_t base = sb + (uint32_t)buf * STAGEB;
#pragma unroll
        for (int it = 0; it < 2; it++) {
            int c = tid + it * 256;            // 0..511
            int row = c >> 2, c16 = c & 3;
            uint32_t doff = (uint32_t)row * ROWB + (uint32_t)c16 * 16;
            size_t ga = (size_t)(row0 + row) * EDIM + s * 32 + c16 * 8;
            size_t gw = (size_t)(col0 + row) * EDIM + s * 32 + c16 * 8;
            cp16(base + doff,             Ah + ga);
            cp16(base + TILEB + doff,     Al + ga);
            cp16(base + 2 * TILEB + doff, Wh + gw);
            cp16(base + 3 * TILEB + doff, Wl + gw);
        }
        CP_COMMIT();
    };

    issue_stage(0, 0);
    issue_stage(1, 1);

    float acc[2][8][4];
#pragma unroll
    for (int mt = 0; mt < 2; mt++)
#pragma unroll
        for (int nt = 0; nt < 8; nt++)
#pragma unroll
            for (int i = 0; i < 4; i++) acc[mt][nt][i] = 0.f;

    const int NKT = EDIM / 32;   // 32
    for (int s = 0; s < NKT; s++) {
        if (s + 1 < NKT) { CP_WAIT(1); } else { CP_WAIT(0); }
        __syncthreads();

        const uint32_t base = sb + (uint32_t)(s & 1) * STAGEB;
#pragma unroll
        for (int ks = 0; ks < 2; ks++) {
            const uint32_t koff = ks * 32;
            uint32_t afr[2][2][4];
#pragma unroll
            for (int sp = 0; sp < 2; sp++)
#pragma unroll
                for (int mt = 0; mt < 2; mt++)
                    ldsm_x4(afr[sp][mt],
                            base + sp * TILEB + (uint32_t)(warp_m + mt * 16) * ROWB
                                 + koff + a_loff);
#pragma unroll
            for (int np = 0; np < 4; np++) {
                uint32_t bh[4], bl[4];
                uint32_t bb = base + (uint32_t)(warp_n + np * 16) * ROWB + koff + b_loff;
                ldsm_x4(bh, bb + 2 * TILEB);
                ldsm_x4(bl, bb + 3 * TILEB);
#pragma unroll
                for (int mt = 0; mt < 2; mt++) {
                    mma16816(acc[mt][2 * np + 0], afr[0][mt], &bh[0]);
                    mma16816(acc[mt][2 * np + 1], afr[0][mt], &bh[2]);
                    mma16816(acc[mt][2 * np + 0], afr[0][mt], &bl[0]);
                    mma16816(acc[mt][2 * np + 1], afr[0][mt], &bl[2]);
                    mma16816(acc[mt][2 * np + 0], afr[1][mt], &bh[0]);
                    mma16816(acc[mt][2 * np + 1], afr[1][mt], &bh[2]);
                }
            }
        }

        __syncthreads();
        if (s + 2 < NKT) issue_stage(s + 2, s & 1);
    }

    const int g   = lane >> 2;
    const int tig = lane & 3;
#pragma unroll
    for (int mt = 0; mt < 2; mt++) {
        int r = row0 + warp_m + mt * 16 + g;
#pragma unroll
        for (int nt = 0; nt < 8; nt++) {
            int col = col0 + warp_n + nt * 8 + 2 * tig;
            if (SPLIT_OUT) {
                uint32_t h, l;
                split_pair(acc[mt][nt][0], acc[mt][nt][1], h, l);
                *(uint32_t*)(Ch + (size_t)r * EDIM + col) = h;
                *(uint32_t*)(Cl + (size_t)r * EDIM + col) = l;
                split_pair(acc[mt][nt][2], acc[mt][nt][3], h, l);
                *(uint32_t*)(Ch + (size_t)(r + 8) * EDIM + col) = h;
                *(uint32_t*)(Cl + (size_t)(r + 8) * EDIM + col) = l;
            } else {
                float bx = bias[col], by = bias[col + 1];
                *(float2*)(C + (size_t)r * EDIM + col) =
                    make_float2(acc[mt][nt][0] + bx, acc[mt][nt][1] + by);
                *(float2*)(C + (size_t)(r + 8) * EDIM + col) =
                    make_float2(acc[mt][nt][2] + bx, acc[mt][nt][3] + by);
            }
        }
    }
}

// ---------------------------------------------------------------------------
// Flash attention on HMMA, fused per-16-key pipeline, Bc=64, 2 CTAs/SM.
// Softmax over UNSCALED scores (faithful reference bug), no running max
// (bounded scores; shift invariance). Br=128, 8 warps x 16 q-rows.
// For each 16-key block: QK (24 mma) -> exp (8 MUFU) -> pack -> PV (24 mma).
// S never materialized beyond one block: ~115 live regs -> 2 CTAs/SM.
// Smem/stage: Khi|Klo|Vhi|Vlo, each 64 x 144 B = 9216 B; 2 stages = 73728 B.
// ---------------------------------------------------------------------------
#define KROWB   144
#define KTILE   (64 * KROWB)                 // 9216
#define FA_STAGE (4 * KTILE)                 // 36864
#define FA_SMEM  (2 * FA_STAGE)              // 73728

__global__ __launch_bounds__(256, 2)
void flash_hmma(const __nv_bfloat16* __restrict__ qh, const __nv_bfloat16* __restrict__ ql,
                const __nv_bfloat16* __restrict__ kh, const __nv_bfloat16* __restrict__ kl,
                const __nv_bfloat16* __restrict__ vh, const __nv_bfloat16* __restrict__ vl,
                __nv_bfloat16* __restrict__ oh, __nv_bfloat16* __restrict__ ol)
{
    extern __shared__ char sm[];
    const uint32_t sb = smem_u32(sm);
    const int tid  = threadIdx.x;
    const int wid  = tid >> 5;
    const int lane = tid & 31;
    const int warp_m = wid * 16;

    const int qt = blockIdx.x;
    const int h  = blockIdx.y;
    const int b  = blockIdx.z;
    const size_t baseRow = (size_t)b * SEQ;
    const int hcol = h * HD;

    const uint32_t a_loff  = (uint32_t)(lane & 15) * KROWB + ((lane & 16) ? 16u : 0u);
    const uint32_t bk_loff = (uint32_t)((lane & 7) + ((lane & 16) ? 8 : 0)) * KROWB
                           + ((lane & 8) ? 16u : 0u);
    const uint32_t bv_loff = (uint32_t)((lane & 7) + ((lane & 8) ? 8 : 0)) * KROWB
                           + ((lane & 16) ? 16u : 0u);

    // ---- stage Q (128 rows hi+lo = 36864 B, fits stage 0), pull A-frags ----
    {
#pragma unroll
        for (int it = 0; it < 4; it++) {
            int c = tid + it * 256;          // 0..1023
            int row = c >> 3, ch = c & 7;
            uint32_t doff = (uint32_t)row * KROWB + (uint32_t)ch * 16;
            size_t ga = (baseRow + qt * 128 + row) * EDIM + hcol + ch * 8;
            cp16(sb + doff,                 qh + ga);
            cp16(sb + 2 * KTILE + doff,     ql + ga);
        }
        CP_COMMIT();
        CP_WAIT(0);
        __syncthreads();
    }
    uint32_t qfr[2][4][4];
#pragma unroll
    for (int sp = 0; sp < 2; sp++)
#pragma unroll
        for (int ks = 0; ks < 4; ks++)
            ldsm_x4(qfr[sp][ks],
                    sb + sp * 2 * KTILE + (uint32_t)warp_m * KROWB + ks * 32 + a_loff);
    __syncthreads();   // all warps done with Q before K/V overwrite

    auto issue_kv = [&](int t, int buf) {
        const uint32_t base = sb + (uint32_t)buf * FA_STAGE;
#pragma unroll
        for (int it = 0; it < 2; it++) {
            int c = tid + it * 256;          // 0..511 (64 rows x 8 chunks)
            int row = c >> 3, ch = c & 7;
            uint32_t doff = (uint32_t)row * KROWB + (uint32_t)ch * 16;
            size_t ga = (baseRow + t * 64 + row) * EDIM + hcol + ch * 8;
            cp16(base + doff,             kh + ga);
            cp16(base + KTILE + doff,     kl + ga);
            cp16(base + 2 * KTILE + doff, vh + ga);
            cp16(base + 3 * KTILE + doff, vl + ga);
        }
        CP_COMMIT();
    };

    issue_kv(0, 0);
    issue_kv(1, 1);

    float Oa[8][4];
#pragma unroll
    for (int i = 0; i < 8; i++)
#pragma unroll
        for (int c = 0; c < 4; c++) Oa[i][c] = 0.f;
    float l0 = 0.f, l1 = 0.f;

    const int NT = SEQ / 64;   // 32
    for (int t = 0; t < NT; t++) {
        if (t + 1 < NT) { CP_WAIT(1); } else { CP_WAIT(0); }
        __syncthreads();

        const uint32_t bs = sb + (uint32_t)(t & 1) * FA_STAGE;
        float rs0 = 0.f, rs1 = 0.f;

        // fused per-16-key block: QK -> exp -> pack -> PV
#pragma unroll
        for (int ng = 0; ng < 4; ng++) {
            float S[2][4];
#pragma unroll
            for (int tt = 0; tt < 2; tt++)
#pragma unroll
                for (int c = 0; c < 4; c++) S[tt][c] = 0.f;

#pragma unroll
            for (int ks = 0; ks < 4; ks++) {
                uint32_t b1[4], b2[4];
                uint32_t kb = bs + (uint32_t)(ng * 16) * KROWB + ks * 32 + bk_loff;
                ldsm_x4(b1, kb);
                ldsm_x4(b2, kb + KTILE);
                mma16816(S[0], qfr[0][ks], &b1[0]);
                mma16816(S[1], qfr[0][ks], &b1[2]);
                mma16816(S[0], qfr[0][ks], &b2[0]);
                mma16816(S[1], qfr[0][ks], &b2[2]);
                mma16816(S[0], qfr[1][ks], &b1[0]);
                mma16816(S[1], qfr[1][ks], &b1[2]);
            }

#pragma unroll
            for (int tt = 0; tt < 2; tt++) {
                S[tt][0] = __expf(S[tt][0]);
                S[tt][1] = __expf(S[tt][1]);
                S[tt][2] = __expf(S[tt][2]);
                S[tt][3] = __expf(S[tt][3]);
                rs0 += S[tt][0] + S[tt][1];
                rs1 += S[tt][2] + S[tt][3];
            }

            uint32_t p1[4], p2[4];
#pragma unroll
            for (int tt = 0; tt < 2; tt++)
#pragma unroll
                for (int hl = 0; hl < 2; hl++)
                    split_pair(S[tt][2 * hl + 0], S[tt][2 * hl + 1],
                               p1[tt * 2 + hl], p2[tt * 2 + hl]);

#pragma unroll
            for (int dg = 0; dg < 4; dg++) {
                uint32_t v1[4], v2[4];
                uint32_t vb = bs + 2 * KTILE + (uint32_t)(ng * 16) * KROWB
                            + dg * 32 + bv_loff;
                ldsm_x4_t(v1, vb);
                ldsm_x4_t(v2, vb + KTILE);
                mma16816(Oa[dg * 2 + 0], p1, &v1[0]);
                mma16816(Oa[dg * 2 + 1], p1, &v1[2]);
                mma16816(Oa[dg * 2 + 0], p1, &v2[0]);
                mma16816(Oa[dg * 2 + 1], p1, &v2[2]);
                mma16816(Oa[dg * 2 + 0], p2, &v1[0]);
                mma16816(Oa[dg * 2 + 1], p2, &v1[2]);
            }
        }

        rs0 += __shfl_xor_sync(0xffffffffu, rs0, 1);
        rs0 += __shfl_xor_sync(0xffffffffu, rs0, 2);
        rs1 += __shfl_xor_sync(0xffffffffu, rs1, 1);
        rs1 += __shfl_xor_sync(0xffffffffu, rs1, 2);
        l0 += rs0;
        l1 += rs1;

        __syncthreads();
        if (t + 2 < NT) issue_kv(t + 2, t & 1);
    }

    // ---- normalize & write split output ----
    const int g   = lane >> 2;
    const int tq2 = (lane & 3) * 2;
    const float inv0 = 1.0f / l0;
    const float inv1 = 1.0f / l1;
    const size_t r0 = (baseRow + qt * 128 + warp_m + g) * EDIM + hcol;
    const size_t r1 = r0 + (size_t)8 * EDIM;
#pragma unroll
    for (int i = 0; i < 8; i++) {
        int d = i * 8 + tq2;
        uint32_t hw, lw;
        split_pair(Oa[i][0] * inv0, Oa[i][1] * inv0, hw, lw);
        *(uint32_t*)(oh + r0 + d) = hw;
        *(uint32_t*)(ol + r0 + d) = lw;
        split_pair(Oa[i][2] * inv1, Oa[i][3] * inv1, hw, lw);
        *(uint32_t*)(oh + r1 + d) = hw;
        *(uint32_t*)(ol + r1 + d) = lw;
    }
}

// ---------------------------------------------------------------------------
extern "C" void kernel_launch(void* const* d_in, const int* in_sizes, int n_in,
                              void* d_out, int out_size)
{
    (void)in_sizes; (void)n_in; (void)out_size;

    const float* Q  = (const float*)d_in[0];
    const float* K  = (const float*)d_in[1];
    const float* V  = (const float*)d_in[2];
    const float* Wq = (const float*)d_in[3];
    const float* Wk = (const float*)d_in[4];
    const float* Wv = (const float*)d_in[5];
    const float* Wo = (const float*)d_in[6];
    const float* bo = (const float*)d_in[7];
    float* out = (float*)d_out;

    __nv_bfloat16 *ah, *al, *wh, *wl, *qh, *ql, *kh, *kl, *vh, *vl;
    cudaGetSymbolAddress((void**)&ah, g_ah);
    cudaGetSymbolAddress((void**)&al, g_al);
    cudaGetSymbolAddress((void**)&wh, g_wh);
    cudaGetSymbolAddress((void**)&wl, g_wl);
    cudaGetSymbolAddress((void**)&qh, g_qh);
    cudaGetSymbolAddress((void**)&ql, g_ql);
    cudaGetSymbolAddress((void**)&kh, g_kh);
    cudaGetSymbolAddress((void**)&kl, g_kl);
    cudaGetSymbolAddress((void**)&vh, g_vh);
    cudaGetSymbolAddress((void**)&vl, g_vl);

    cudaFuncSetAttribute(gemm_hmma<true>,
                         cudaFuncAttributeMaxDynamicSharedMemorySize, GEMM_SMEM);
    cudaFuncSetAttribute(gemm_hmma<false>,
                         cudaFuncAttributeMaxDynamicSharedMemorySize, GEMM_SMEM);
    cudaFuncSetAttribute(flash_hmma,
                         cudaFuncAttributeMaxDynamicSharedMemorySize, FA_SMEM);

    const int nA4 = MTOT * EDIM / 4;
    const int nW4 = EDIM * EDIM / 4;
    dim3 gemmGrid(EDIM / 128, MTOT / 128);

    // Q projection -> split output
    split2_kernel<<<nA4 / 256, 256>>>(Q, ah, al, nA4);
    split2_kernel<<<nW4 / 256, 256>>>(Wq, wh, wl, nW4);
    gemm_hmma<true><<<gemmGrid, 256, GEMM_SMEM>>>(ah, al, wh, wl, nullptr,
                                                  nullptr, qh, ql);
    // K projection
    split2_kernel<<<nA4 / 256, 256>>>(K, ah, al, nA4);
    split2_kernel<<<nW4 / 256, 256>>>(Wk, wh, wl, nW4);
    gemm_hmma<true><<<gemmGrid, 256, GEMM_SMEM>>>(ah, al, wh, wl, nullptr,
                                                  nullptr, kh, kl);
    // V projection
    split2_kernel<<<nA4 / 256, 256>>>(V, ah, al, nA4);
    split2_kernel<<<nW4 / 256, 256>>>(Wv, wh, wl, nW4);
    gemm_hmma<true><<<gemmGrid, 256, GEMM_SMEM>>>(ah, al, wh, wl, nullptr,
                                                  nullptr, vh, vl);

    // Attention, split output into (ah, al)
    flash_hmma<<<dim3(SEQ / 128, NH, NB), 256, FA_SMEM>>>(qh, ql, kh, kl,
                                                          vh, vl, ah, al);

    // Output projection (+bias), fp32 out
    split2_kernel<<<nW4 / 256, 256>>>(Wo, wh, wl, nW4);
    gemm_hmma<false><<<gemmGrid, 256, GEMM_SMEM>>>(ah, al, wh, wl, bo,
                                                   out, nullptr, nullptr);
}

// round 8
// speedup vs baseline: 2.9635x; 1.0891x over previous
#include <cuda_runtime.h>
#include <cuda_bf16.h>
#include <cstdint>

#define EDIM 1024
#define NH   16
#define HD   64
#define NB   4
#define SEQ  2048
#define MTOT (NB*SEQ)   // 8192 rows
#define SLOT ((size_t)MTOT * EDIM)
#define WSLOT ((size_t)EDIM * EDIM)

// ---------------------------------------------------------------------------
// Scratch: z-indexed split buffers.
// g_xh/g_xl: slot 0..2 = split inputs Q,K,V; slot 0 reused for attn output.
// g_ph/g_pl: slot 0..2 = projected q,k,v splits.
// g_wh/g_wl: slot 0..3 = split Wq,Wk,Wv,Wo.
// ---------------------------------------------------------------------------
__device__ __nv_bfloat16 g_xh[3 * SLOT];
__device__ __nv_bfloat16 g_xl[3 * SLOT];
__device__ __nv_bfloat16 g_ph[3 * SLOT];
__device__ __nv_bfloat16 g_pl[3 * SLOT];
__device__ __nv_bfloat16 g_wh[4 * WSLOT];
__device__ __nv_bfloat16 g_wl[4 * WSLOT];

// ---------------------------------------------------------------------------
// helpers
// ---------------------------------------------------------------------------
__device__ __forceinline__ uint32_t smem_u32(const void* p) {
    uint32_t a;
    asm("{ .reg .u64 t; cvta.to.shared.u64 t, %1; cvt.u32.u64 %0, t; }"
        : "=r"(a) : "l"(p));
    return a;
}

__device__ __forceinline__ void ldsm_x4(uint32_t* r, uint32_t addr) {
    asm volatile("ldmatrix.sync.aligned.m8n8.x4.shared.b16 {%0,%1,%2,%3}, [%4];"
                 : "=r"(r[0]), "=r"(r[1]), "=r"(r[2]), "=r"(r[3]) : "r"(addr));
}

__device__ __forceinline__ void ldsm_x4_t(uint32_t* r, uint32_t addr) {
    asm volatile("ldmatrix.sync.aligned.m8n8.x4.trans.shared.b16 {%0,%1,%2,%3}, [%4];"
                 : "=r"(r[0]), "=r"(r[1]), "=r"(r[2]), "=r"(r[3]) : "r"(addr));
}

__device__ __forceinline__ void mma16816(float* d, const uint32_t* a,
                                         const uint32_t* b) {
    asm volatile(
        "mma.sync.aligned.m16n8k16.row.col.f32.bf16.bf16.f32 "
        "{%0,%1,%2,%3}, {%4,%5,%6,%7}, {%8,%9}, {%0,%1,%2,%3};"
        : "+f"(d[0]), "+f"(d[1]), "+f"(d[2]), "+f"(d[3])
        : "r"(a[0]), "r"(a[1]), "r"(a[2]), "r"(a[3]), "r"(b[0]), "r"(b[1]));
}

__device__ __forceinline__ void cp16(uint32_t smem_dst, const void* gptr) {
    asm volatile("cp.async.cg.shared.global [%0], [%1], 16;"
                 :: "r"(smem_dst), "l"(gptr));
}
#define CP_COMMIT() asm volatile("cp.async.commit_group;")
#define CP_WAIT(n)  asm volatile("cp.async.wait_group %0;" :: "n"(n))

__device__ __forceinline__ void split_pair(float x, float y,
                                           uint32_t& hi, uint32_t& lo) {
    __nv_bfloat16 hx = __float2bfloat16_rn(x);
    __nv_bfloat16 hy = __float2bfloat16_rn(y);
    __nv_bfloat162 h2 = __halves2bfloat162(hx, hy);
    __nv_bfloat162 l2 = __halves2bfloat162(
        __float2bfloat16_rn(x - __bfloat162float(hx)),
        __float2bfloat16_rn(y - __bfloat162float(hy)));
    hi = *reinterpret_cast<uint32_t*>(&h2);
    lo = *reinterpret_cast<uint32_t*>(&l2);
}

// ---------------------------------------------------------------------------
// split passes (z-indexed)
// ---------------------------------------------------------------------------
__global__ void split_in_kernel(const float* __restrict__ q, const float* __restrict__ k,
                                const float* __restrict__ v,
                                __nv_bfloat16* __restrict__ oh,
                                __nv_bfloat16* __restrict__ ol, int n4)
{
    int z = blockIdx.y;
    const float* x = (z == 0) ? q : (z == 1) ? k : v;
    oh += (size_t)z * SLOT;
    ol += (size_t)z * SLOT;
    int i = blockIdx.x * blockDim.x + threadIdx.x;
    if (i >= n4) return;
    float4 vv = reinterpret_cast<const float4*>(x)[i];
    uint32_t h0, l0, h1, l1;
    split_pair(vv.x, vv.y, h0, l0);
    split_pair(vv.z, vv.w, h1, l1);
    reinterpret_cast<uint2*>(oh)[i] = make_uint2(h0, h1);
    reinterpret_cast<uint2*>(ol)[i] = make_uint2(l0, l1);
}

__global__ void split_w_kernel(const float* __restrict__ w0, const float* __restrict__ w1,
                               const float* __restrict__ w2, const float* __restrict__ w3,
                               __nv_bfloat16* __restrict__ oh,
                               __nv_bfloat16* __restrict__ ol, int n4)
{
    int z = blockIdx.y;
    const float* x = (z == 0) ? w0 : (z == 1) ? w1 : (z == 2) ? w2 : w3;
    oh += (size_t)z * WSLOT;
    ol += (size_t)z * WSLOT;
    int i = blockIdx.x * blockDim.x + threadIdx.x;
    if (i >= n4) return;
    float4 vv = reinterpret_cast<const float4*>(x)[i];
    uint32_t h0, l0, h1, l1;
    split_pair(vv.x, vv.y, h0, l0);
    split_pair(vv.z, vv.w, h1, l1);
    reinterpret_cast<uint2*>(oh)[i] = make_uint2(h0, h1);
    reinterpret_cast<uint2*>(ol)[i] = make_uint2(l0, l1);
}

// ---------------------------------------------------------------------------
// HMMA GEMM: C = A * W^T, 3 products, pre-split bf16.
// CTA tile 128x128, BK=32, 4 warps (warp tile 64x64), 128 threads,
// 2-stage cp.async pipeline, 2 CTAs/SM. z-indexed operand slots.
// ---------------------------------------------------------------------------
#define ROWB        80                   // 32 bf16 + 16B pad
#define TILEB       (128 * ROWB)         // 10240
#define STAGEB      (4 * TILEB)          // 40960
#define GEMM_SMEM   (2 * STAGEB)         // 81920

template<bool SPLIT_OUT>
__global__ __launch_bounds__(128, 2)
void gemm_hmma(const __nv_bfloat16* __restrict__ Ah, const __nv_bfloat16* __restrict__ Al,
               const __nv_bfloat16* __restrict__ Wh, const __nv_bfloat16* __restrict__ Wl,
               const float* __restrict__ bias,
               float* __restrict__ C,
               __nv_bfloat16* __restrict__ Ch, __nv_bfloat16* __restrict__ Cl)
{
    extern __shared__ char smem[];
    const uint32_t sb = smem_u32(smem);
    const int tid  = threadIdx.x;
    const int wid  = tid >> 5;
    const int lane = tid & 31;
    const int row0 = blockIdx.y * 128;
    const int col0 = blockIdx.x * 128;
    const int z    = blockIdx.z;
    const int warp_m = (wid & 1) * 64;
    const int warp_n = (wid >> 1) * 64;

    Ah += (size_t)z * SLOT;  Al += (size_t)z * SLOT;
    Wh += (size_t)z * WSLOT; Wl += (size_t)z * WSLOT;

    const uint32_t a_loff = (uint32_t)(lane & 15) * ROWB + ((lane & 16) ? 16u : 0u);
    const uint32_t b_loff = (uint32_t)((lane & 7) + ((lane & 16) ? 8 : 0)) * ROWB
                          + ((lane & 8) ? 16u : 0u);

    auto issue_stage = [&](int s, int buf) {
        const uint32_t base = sb + (uint32_t)buf * STAGEB;
#pragma unroll
        for (int it = 0; it < 4; it++) {
            int c = tid + it * 128;            // 0..511
            int row = c >> 2, c16 = c & 3;
            uint32_t doff = (uint32_t)row * ROWB + (uint32_t)c16 * 16;
            size_t ga = (size_t)(row0 + row) * EDIM + s * 32 + c16 * 8;
            size_t gw = (size_t)(col0 + row) * EDIM + s * 32 + c16 * 8;
            cp16(base + doff,             Ah + ga);
            cp16(base + TILEB + doff,     Al + ga);
            cp16(base + 2 * TILEB + doff, Wh + gw);
            cp16(base + 3 * TILEB + doff, Wl + gw);
        }
        CP_COMMIT();
    };

    issue_stage(0, 0);
    issue_stage(1, 1);

    float acc[4][8][4];
#pragma unroll
    for (int mt = 0; mt < 4; mt++)
#pragma unroll
        for (int nt = 0; nt < 8; nt++)
#pragma unroll
            for (int i = 0; i < 4; i++) acc[mt][nt][i] = 0.f;

    const int NKT = EDIM / 32;   // 32
    for (int s = 0; s < NKT; s++) {
        if (s + 1 < NKT) { CP_WAIT(1); } else { CP_WAIT(0); }
        __syncthreads();

        const uint32_t base = sb + (uint32_t)(s & 1) * STAGEB;
#pragma unroll
        for (int ks = 0; ks < 2; ks++) {
            const uint32_t koff = ks * 32;
            uint32_t afr[2][4][4];
#pragma unroll
            for (int sp = 0; sp < 2; sp++)
#pragma unroll
                for (int mt = 0; mt < 4; mt++)
                    ldsm_x4(afr[sp][mt],
                            base + sp * TILEB + (uint32_t)(warp_m + mt * 16) * ROWB
                                 + koff + a_loff);
#pragma unroll
            for (int np = 0; np < 4; np++) {
                uint32_t bh[4], bl[4];
                uint32_t bb = base + (uint32_t)(warp_n + np * 16) * ROWB + koff + b_loff;
                ldsm_x4(bh, bb + 2 * TILEB);
                ldsm_x4(bl, bb + 3 * TILEB);
#pragma unroll
                for (int mt = 0; mt < 4; mt++) {
                    mma16816(acc[mt][2 * np + 0], afr[0][mt], &bh[0]);
                    mma16816(acc[mt][2 * np + 1], afr[0][mt], &bh[2]);
                    mma16816(acc[mt][2 * np + 0], afr[0][mt], &bl[0]);
                    mma16816(acc[mt][2 * np + 1], afr[0][mt], &bl[2]);
                    mma16816(acc[mt][2 * np + 0], afr[1][mt], &bh[0]);
                    mma16816(acc[mt][2 * np + 1], afr[1][mt], &bh[2]);
                }
            }
        }

        __syncthreads();
        if (s + 2 < NKT) issue_stage(s + 2, s & 1);
    }

    const int g   = lane >> 2;
    const int tig = lane & 3;
#pragma unroll
    for (int mt = 0; mt < 4; mt++) {
        int r = row0 + warp_m + mt * 16 + g;
#pragma unroll
        for (int nt = 0; nt < 8; nt++) {
            int col = col0 + warp_n + nt * 8 + 2 * tig;
            if (SPLIT_OUT) {
                uint32_t hw, lw;
                split_pair(acc[mt][nt][0], acc[mt][nt][1], hw, lw);
                *(uint32_t*)(Ch + (size_t)z * SLOT + (size_t)r * EDIM + col) = hw;
                *(uint32_t*)(Cl + (size_t)z * SLOT + (size_t)r * EDIM + col) = lw;
                split_pair(acc[mt][nt][2], acc[mt][nt][3], hw, lw);
                *(uint32_t*)(Ch + (size_t)z * SLOT + (size_t)(r + 8) * EDIM + col) = hw;
                *(uint32_t*)(Cl + (size_t)z * SLOT + (size_t)(r + 8) * EDIM + col) = lw;
            } else {
                float bx = bias[col], by = bias[col + 1];
                *(float2*)(C + (size_t)r * EDIM + col) =
                    make_float2(acc[mt][nt][0] + bx, acc[mt][nt][1] + by);
                *(float2*)(C + (size_t)(r + 8) * EDIM + col) =
                    make_float2(acc[mt][nt][2] + bx, acc[mt][nt][3] + by);
            }
        }
    }
}

// ---------------------------------------------------------------------------
// Flash attention on HMMA. 4 warps x 32 q-rows (Br=128), Bc=64, fused
// per-16-key block, 2 CTAs/SM. Softmax over UNSCALED scores (faithful
// reference bug), no running max (bounded scores; shift invariance).
// Smem/stage: Khi|Klo|Vhi|Vlo, each 64 x 144 B = 9216 B; 2 stages.
// ---------------------------------------------------------------------------
#define KROWB    144
#define KTILE    (64 * KROWB)                // 9216
#define QTILE    (128 * KROWB)               // 18432
#define FA_STAGE (4 * KTILE)                 // 36864
#define FA_SMEM  (2 * FA_STAGE)              // 73728

__global__ __launch_bounds__(128, 2)
void flash_hmma(const __nv_bfloat16* __restrict__ ph, const __nv_bfloat16* __restrict__ pl,
                __nv_bfloat16* __restrict__ oh, __nv_bfloat16* __restrict__ ol)
{
    extern __shared__ char sm[];
    const uint32_t sb = smem_u32(sm);
    const int tid  = threadIdx.x;
    const int wid  = tid >> 5;
    const int lane = tid & 31;
    const int warp_m = wid * 32;

    const int qt = blockIdx.x;
    const int h  = blockIdx.y;
    const int b  = blockIdx.z;
    const size_t baseRow = (size_t)b * SEQ;
    const int hcol = h * HD;

    const __nv_bfloat16* qh = ph;
    const __nv_bfloat16* ql = pl;
    const __nv_bfloat16* kh = ph + SLOT;
    const __nv_bfloat16* kl = pl + SLOT;
    const __nv_bfloat16* vh = ph + 2 * SLOT;
    const __nv_bfloat16* vl = pl + 2 * SLOT;

    const uint32_t a_loff  = (uint32_t)(lane & 15) * KROWB + ((lane & 16) ? 16u : 0u);
    const uint32_t bk_loff = (uint32_t)((lane & 7) + ((lane & 16) ? 8 : 0)) * KROWB
                           + ((lane & 8) ? 16u : 0u);
    const uint32_t bv_loff = (uint32_t)((lane & 7) + ((lane & 8) ? 8 : 0)) * KROWB
                           + ((lane & 16) ? 16u : 0u);

    // ---- stage Q (hi at 0, lo at QTILE), pull A-fragments ----
    {
#pragma unroll
        for (int it = 0; it < 8; it++) {
            int c = tid + it * 128;          // 0..1023
            int row = c >> 3, ch = c & 7;
            uint32_t doff = (uint32_t)row * KROWB + (uint32_t)ch * 16;
            size_t ga = (baseRow + qt * 128 + row) * EDIM + hcol + ch * 8;
            cp16(sb + doff,         qh + ga);
            cp16(sb + QTILE + doff, ql + ga);
        }
        CP_COMMIT();
        CP_WAIT(0);
        __syncthreads();
    }
    uint32_t qfr[2][4][2][4];   // [split][kstep][mt][frag]
#pragma unroll
    for (int sp = 0; sp < 2; sp++)
#pragma unroll
        for (int ks = 0; ks < 4; ks++)
#pragma unroll
            for (int mt = 0; mt < 2; mt++)
                ldsm_x4(qfr[sp][ks][mt],
                        sb + sp * QTILE + (uint32_t)(warp_m + mt * 16) * KROWB
                             + ks * 32 + a_loff);
    __syncthreads();

    auto issue_kv = [&](int t, int buf) {
        const uint32_t base = sb + (uint32_t)buf * FA_STAGE;
#pragma unroll
        for (int it = 0; it < 4; it++) {
            int c = tid + it * 128;          // 0..511
            int row = c >> 3, ch = c & 7;
            uint32_t doff = (uint32_t)row * KROWB + (uint32_t)ch * 16;
            size_t ga = (baseRow + t * 64 + row) * EDIM + hcol + ch * 8;
            cp16(base + doff,             kh + ga);
            cp16(base + KTILE + doff,     kl + ga);
            cp16(base + 2 * KTILE + doff, vh + ga);
            cp16(base + 3 * KTILE + doff, vl + ga);
        }
        CP_COMMIT();
    };

    issue_kv(0, 0);
    issue_kv(1, 1);

    float Oa[2][8][4];
#pragma unroll
    for (int mt = 0; mt < 2; mt++)
#pragma unroll
        for (int i = 0; i < 8; i++)
#pragma unroll
            for (int c = 0; c < 4; c++) Oa[mt][i][c] = 0.f;
    float lsum[2][2] = {{0.f, 0.f}, {0.f, 0.f}};

    const int NT = SEQ / 64;   // 32
    for (int t = 0; t < NT; t++) {
        if (t + 1 < NT) { CP_WAIT(1); } else { CP_WAIT(0); }
        __syncthreads();

        const uint32_t bs = sb + (uint32_t)(t & 1) * FA_STAGE;
        float rs[2][2] = {{0.f, 0.f}, {0.f, 0.f}};

        // fused per-16-key block: QK -> exp -> pack -> PV
#pragma unroll
        for (int ng = 0; ng < 4; ng++) {
            float S[2][2][4];
#pragma unroll
            for (int mt = 0; mt < 2; mt++)
#pragma unroll
                for (int tt = 0; tt < 2; tt++)
#pragma unroll
                    for (int c = 0; c < 4; c++) S[mt][tt][c] = 0.f;

#pragma unroll
            for (int ks = 0; ks < 4; ks++) {
                uint32_t b1[4], b2[4];
                uint32_t kb = bs + (uint32_t)(ng * 16) * KROWB + ks * 32 + bk_loff;
                ldsm_x4(b1, kb);
                ldsm_x4(b2, kb + KTILE);
#pragma unroll
                for (int mt = 0; mt < 2; mt++) {
                    mma16816(S[mt][0], qfr[0][ks][mt], &b1[0]);
                    mma16816(S[mt][1], qfr[0][ks][mt], &b1[2]);
                    mma16816(S[mt][0], qfr[0][ks][mt], &b2[0]);
                    mma16816(S[mt][1], qfr[0][ks][mt], &b2[2]);
                    mma16816(S[mt][0], qfr[1][ks][mt], &b1[0]);
                    mma16816(S[mt][1], qfr[1][ks][mt], &b1[2]);
                }
            }

            uint32_t p1[2][4], p2[2][4];
#pragma unroll
            for (int mt = 0; mt < 2; mt++) {
#pragma unroll
                for (int tt = 0; tt < 2; tt++) {
                    S[mt][tt][0] = __expf(S[mt][tt][0]);
                    S[mt][tt][1] = __expf(S[mt][tt][1]);
                    S[mt][tt][2] = __expf(S[mt][tt][2]);
                    S[mt][tt][3] = __expf(S[mt][tt][3]);
                    rs[mt][0] += S[mt][tt][0] + S[mt][tt][1];
                    rs[mt][1] += S[mt][tt][2] + S[mt][tt][3];
                }
#pragma unroll
                for (int tt = 0; tt < 2; tt++)
#pragma unroll
                    for (int hl = 0; hl < 2; hl++)
                        split_pair(S[mt][tt][2 * hl + 0], S[mt][tt][2 * hl + 1],
                                   p1[mt][tt * 2 + hl], p2[mt][tt * 2 + hl]);
            }

#pragma unroll
            for (int dg = 0; dg < 4; dg++) {
                uint32_t v1[4], v2[4];
                uint32_t vb = bs + 2 * KTILE + (uint32_t)(ng * 16) * KROWB
                            + dg * 32 + bv_loff;
                ldsm_x4_t(v1, vb);
                ldsm_x4_t(v2, vb + KTILE);
#pragma unroll
                for (int mt = 0; mt < 2; mt++) {
                    mma16816(Oa[mt][dg * 2 + 0], p1[mt], &v1[0]);
                    mma16816(Oa[mt][dg * 2 + 1], p1[mt], &v1[2]);
                    mma16816(Oa[mt][dg * 2 + 0], p1[mt], &v2[0]);
                    mma16816(Oa[mt][dg * 2 + 1], p1[mt], &v2[2]);
                    mma16816(Oa[mt][dg * 2 + 0], p2[mt], &v1[0]);
                    mma16816(Oa[mt][dg * 2 + 1], p2[mt], &v1[2]);
                }
            }
        }

#pragma unroll
        for (int mt = 0; mt < 2; mt++)
#pragma unroll
            for (int j = 0; j < 2; j++) {
                float r = rs[mt][j];
                r += __shfl_xor_sync(0xffffffffu, r, 1);
                r += __shfl_xor_sync(0xffffffffu, r, 2);
                lsum[mt][j] += r;
            }

        __syncthreads();
        if (t + 2 < NT) issue_kv(t + 2, t & 1);
    }

    // ---- normalize & write split output into slot 0 of (oh, ol) ----
    const int g   = lane >> 2;
    const int tq2 = (lane & 3) * 2;
#pragma unroll
    for (int mt = 0; mt < 2; mt++) {
        const float inv0 = 1.0f / lsum[mt][0];
        const float inv1 = 1.0f / lsum[mt][1];
        const size_t r0 = (baseRow + qt * 128 + warp_m + mt * 16 + g) * EDIM + hcol;
        const size_t r1 = r0 + (size_t)8 * EDIM;
#pragma unroll
        for (int i = 0; i < 8; i++) {
            int d = i * 8 + tq2;
            uint32_t hw, lw;
            split_pair(Oa[mt][i][0] * inv0, Oa[mt][i][1] * inv0, hw, lw);
            *(uint32_t*)(oh + r0 + d) = hw;
            *(uint32_t*)(ol + r0 + d) = lw;
            split_pair(Oa[mt][i][2] * inv1, Oa[mt][i][3] * inv1, hw, lw);
            *(uint32_t*)(oh + r1 + d) = hw;
            *(uint32_t*)(ol + r1 + d) = lw;
        }
    }
}

// ---------------------------------------------------------------------------
extern "C" void kernel_launch(void* const* d_in, const int* in_sizes, int n_in,
                              void* d_out, int out_size)
{
    (void)in_sizes; (void)n_in; (void)out_size;

    const float* Q  = (const float*)d_in[0];
    const float* K  = (const float*)d_in[1];
    const float* V  = (const float*)d_in[2];
    const float* Wq = (const float*)d_in[3];
    const float* Wk = (const float*)d_in[4];
    const float* Wv = (const float*)d_in[5];
    const float* Wo = (const float*)d_in[6];
    const float* bo = (const float*)d_in[7];
    float* out = (float*)d_out;

    __nv_bfloat16 *xh, *xl, *phb, *plb, *wh, *wl;
    cudaGetSymbolAddress((void**)&xh, g_xh);
    cudaGetSymbolAddress((void**)&xl, g_xl);
    cudaGetSymbolAddress((void**)&phb, g_ph);
    cudaGetSymbolAddress((void**)&plb, g_pl);
    cudaGetSymbolAddress((void**)&wh, g_wh);
    cudaGetSymbolAddress((void**)&wl, g_wl);

    cudaFuncSetAttribute(gemm_hmma<true>,
                         cudaFuncAttributeMaxDynamicSharedMemorySize, GEMM_SMEM);
    cudaFuncSetAttribute(gemm_hmma<false>,
                         cudaFuncAttributeMaxDynamicSharedMemorySize, GEMM_SMEM);
    cudaFuncSetAttribute(flash_hmma,
                         cudaFuncAttributeMaxDynamicSharedMemorySize, FA_SMEM);

    const int nA4 = MTOT * EDIM / 4;
    const int nW4 = EDIM * EDIM / 4;

    // split inputs (z = Q,K,V) and weights (z = Wq,Wk,Wv,Wo)
    split_in_kernel<<<dim3(nA4 / 256, 3), 256>>>(Q, K, V, xh, xl, nA4);
    split_w_kernel<<<dim3(nW4 / 256, 4), 256>>>(Wq, Wk, Wv, Wo, wh, wl, nW4);

    // fused QKV projections (z-indexed), split outputs
    gemm_hmma<true><<<dim3(EDIM / 128, MTOT / 128, 3), 128, GEMM_SMEM>>>(
        xh, xl, wh, wl, nullptr, nullptr, phb, plb);

    // attention: reads slots 0..2 of (phb, plb), writes split into slot 0 of (xh, xl)
    flash_hmma<<<dim3(SEQ / 128, NH, NB), 128, FA_SMEM>>>(phb, plb, xh, xl);

    // output projection (+bias), fp32 out; weight slot 3 pre-offset
    gemm_hmma<false><<<dim3(EDIM / 128, MTOT / 128, 1), 128, GEMM_SMEM>>>(
        xh, xl, wh + 3 * WSLOT, wl + 3 * WSLOT, bo, out, nullptr, nullptr);
}

// round 9
// speedup vs baseline: 2.9740x; 1.0036x over previous
#include <cuda_runtime.h>
#include <cuda_bf16.h>
#include <cstdint>

#define EDIM 1024
#define NH   16
#define HD   64
#define NB   4
#define SEQ  2048
#define MTOT (NB*SEQ)   // 8192 rows
#define SLOT ((size_t)MTOT * EDIM)
#define WSLOT ((size_t)EDIM * EDIM)

// ---------------------------------------------------------------------------
// Scratch: z-indexed split buffers.
// ---------------------------------------------------------------------------
__device__ __nv_bfloat16 g_xh[3 * SLOT];
__device__ __nv_bfloat16 g_xl[3 * SLOT];
__device__ __nv_bfloat16 g_ph[3 * SLOT];
__device__ __nv_bfloat16 g_pl[3 * SLOT];
__device__ __nv_bfloat16 g_wh[4 * WSLOT];
__device__ __nv_bfloat16 g_wl[4 * WSLOT];

// ---------------------------------------------------------------------------
// helpers
// ---------------------------------------------------------------------------
__device__ __forceinline__ uint32_t smem_u32(const void* p) {
    uint32_t a;
    asm("{ .reg .u64 t; cvta.to.shared.u64 t, %1; cvt.u32.u64 %0, t; }"
        : "=r"(a) : "l"(p));
    return a;
}

__device__ __forceinline__ void ldsm_x4(uint32_t* r, uint32_t addr) {
    asm volatile("ldmatrix.sync.aligned.m8n8.x4.shared.b16 {%0,%1,%2,%3}, [%4];"
                 : "=r"(r[0]), "=r"(r[1]), "=r"(r[2]), "=r"(r[3]) : "r"(addr));
}

__device__ __forceinline__ void ldsm_x4_t(uint32_t* r, uint32_t addr) {
    asm volatile("ldmatrix.sync.aligned.m8n8.x4.trans.shared.b16 {%0,%1,%2,%3}, [%4];"
                 : "=r"(r[0]), "=r"(r[1]), "=r"(r[2]), "=r"(r[3]) : "r"(addr));
}

__device__ __forceinline__ void mma16816(float* d, const uint32_t* a,
                                         const uint32_t* b) {
    asm volatile(
        "mma.sync.aligned.m16n8k16.row.col.f32.bf16.bf16.f32 "
        "{%0,%1,%2,%3}, {%4,%5,%6,%7}, {%8,%9}, {%0,%1,%2,%3};"
        : "+f"(d[0]), "+f"(d[1]), "+f"(d[2]), "+f"(d[3])
        : "r"(a[0]), "r"(a[1]), "r"(a[2]), "r"(a[3]), "r"(b[0]), "r"(b[1]));
}

__device__ __forceinline__ void cp16(uint32_t smem_dst, const void* gptr) {
    asm volatile("cp.async.cg.shared.global [%0], [%1], 16;"
                 :: "r"(smem_dst), "l"(gptr));
}
#define CP_COMMIT() asm volatile("cp.async.commit_group;")
#define CP_WAIT(n)  asm volatile("cp.async.wait_group %0;" :: "n"(n))

__device__ __forceinline__ void split_pair(float x, float y,
                                           uint32_t& hi, uint32_t& lo) {
    __nv_bfloat16 hx = __float2bfloat16_rn(x);
    __nv_bfloat16 hy = __float2bfloat16_rn(y);
    __nv_bfloat162 h2 = __halves2bfloat162(hx, hy);
    __nv_bfloat162 l2 = __halves2bfloat162(
        __float2bfloat16_rn(x - __bfloat162float(hx)),
        __float2bfloat16_rn(y - __bfloat162float(hy)));
    hi = *reinterpret_cast<uint32_t*>(&h2);
    lo = *reinterpret_cast<uint32_t*>(&l2);
}

// ---------------------------------------------------------------------------
// split passes (z-indexed)
// ---------------------------------------------------------------------------
__global__ void split_in_kernel(const float* __restrict__ q, const float* __restrict__ k,
                                const float* __restrict__ v,
                                __nv_bfloat16* __restrict__ oh,
                                __nv_bfloat16* __restrict__ ol, int n4)
{
    int z = blockIdx.y;
    const float* x = (z == 0) ? q : (z == 1) ? k : v;
    oh += (size_t)z * SLOT;
    ol += (size_t)z * SLOT;
    int i = blockIdx.x * blockDim.x + threadIdx.x;
    if (i >= n4) return;
    float4 vv = reinterpret_cast<const float4*>(x)[i];
    uint32_t h0, l0, h1, l1;
    split_pair(vv.x, vv.y, h0, l0);
    split_pair(vv.z, vv.w, h1, l1);
    reinterpret_cast<uint2*>(oh)[i] = make_uint2(h0, h1);
    reinterpret_cast<uint2*>(ol)[i] = make_uint2(l0, l1);
}

__global__ void split_w_kernel(const float* __restrict__ w0, const float* __restrict__ w1,
                               const float* __restrict__ w2, const float* __restrict__ w3,
                               __nv_bfloat16* __restrict__ oh,
                               __nv_bfloat16* __restrict__ ol, int n4)
{
    int z = blockIdx.y;
    const float* x = (z == 0) ? w0 : (z == 1) ? w1 : (z == 2) ? w2 : w3;
    oh += (size_t)z * WSLOT;
    ol += (size_t)z * WSLOT;
    int i = blockIdx.x * blockDim.x + threadIdx.x;
    if (i >= n4) return;
    float4 vv = reinterpret_cast<const float4*>(x)[i];
    uint32_t h0, l0, h1, l1;
    split_pair(vv.x, vv.y, h0, l0);
    split_pair(vv.z, vv.w, h1, l1);
    reinterpret_cast<uint2*>(oh)[i] = make_uint2(h0, h1);
    reinterpret_cast<uint2*>(ol)[i] = make_uint2(l0, l1);
}

// ---------------------------------------------------------------------------
// HMMA GEMM: C = A * W^T, 3 products, pre-split bf16.
// CTA tile 128x128, BK=16, 4 warps (warp tile 64x64), 128 threads,
// 4-stage cp.async ring, ONE barrier per stage, 2 CTAs/SM.
// Smem rows: 16 bf16 = 32 B + 16 B pad = 48 B (bank stride 12 mod 32:
// conflict-free per 8-lane ldmatrix phase).
// ---------------------------------------------------------------------------
#define ROWB        48
#define TILEB       (128 * ROWB)         // 6144
#define STAGEB      (4 * TILEB)          // 24576
#define GEMM_STAGES 4
#define GEMM_SMEM   (GEMM_STAGES * STAGEB)   // 98304

template<bool SPLIT_OUT>
__global__ __launch_bounds__(128, 2)
void gemm_hmma(const __nv_bfloat16* __restrict__ Ah, const __nv_bfloat16* __restrict__ Al,
               const __nv_bfloat16* __restrict__ Wh, const __nv_bfloat16* __restrict__ Wl,
               const float* __restrict__ bias,
               float* __restrict__ C,
               __nv_bfloat16* __restrict__ Ch, __nv_bfloat16* __restrict__ Cl)
{
    extern __shared__ char smem[];
    const uint32_t sb = smem_u32(smem);
    const int tid  = threadIdx.x;
    const int wid  = tid >> 5;
    const int lane = tid & 31;
    const int row0 = blockIdx.y * 128;
    const int col0 = blockIdx.x * 128;
    const int z    = blockIdx.z;
    const int warp_m = (wid & 1) * 64;
    const int warp_n = (wid >> 1) * 64;

    Ah += (size_t)z * SLOT;  Al += (size_t)z * SLOT;
    Wh += (size_t)z * WSLOT; Wl += (size_t)z * WSLOT;

    const uint32_t a_loff = (uint32_t)(lane & 15) * ROWB + ((lane & 16) ? 16u : 0u);
    const uint32_t b_loff = (uint32_t)((lane & 7) + ((lane & 16) ? 8 : 0)) * ROWB
                          + ((lane & 8) ? 16u : 0u);

    auto issue_stage = [&](int s) {
        const uint32_t base = sb + (uint32_t)(s & 3) * STAGEB;
#pragma unroll
        for (int it = 0; it < 2; it++) {
            int c = tid + it * 128;            // 0..255
            int row = c >> 1, c16 = c & 1;
            uint32_t doff = (uint32_t)row * ROWB + (uint32_t)c16 * 16;
            size_t ga = (size_t)(row0 + row) * EDIM + s * 16 + c16 * 8;
            size_t gw = (size_t)(col0 + row) * EDIM + s * 16 + c16 * 8;
            cp16(base + doff,             Ah + ga);
            cp16(base + TILEB + doff,     Al + ga);
            cp16(base + 2 * TILEB + doff, Wh + gw);
            cp16(base + 3 * TILEB + doff, Wl + gw);
        }
        CP_COMMIT();
    };

    issue_stage(0);
    issue_stage(1);
    issue_stage(2);

    float acc[4][8][4];
#pragma unroll
    for (int mt = 0; mt < 4; mt++)
#pragma unroll
        for (int nt = 0; nt < 8; nt++)
#pragma unroll
            for (int i = 0; i < 4; i++) acc[mt][nt][i] = 0.f;

    const int NKT = EDIM / 16;   // 64
    for (int s = 0; s < NKT; s++) {
        if (s + 3 <= NKT) { CP_WAIT(2); }
        else if (s + 2 <= NKT) { CP_WAIT(1); }
        else { CP_WAIT(0); }
        __syncthreads();
        if (s + 3 < NKT) issue_stage(s + 3);   // target consumed at s-1: safe

        const uint32_t base = sb + (uint32_t)(s & 3) * STAGEB;
        uint32_t afr[2][4][4];
#pragma unroll
        for (int sp = 0; sp < 2; sp++)
#pragma unroll
            for (int mt = 0; mt < 4; mt++)
                ldsm_x4(afr[sp][mt],
                        base + sp * TILEB + (uint32_t)(warp_m + mt * 16) * ROWB + a_loff);
#pragma unroll
        for (int np = 0; np < 4; np++) {
            uint32_t bh[4], bl[4];
            uint32_t bb = base + (uint32_t)(warp_n + np * 16) * ROWB + b_loff;
            ldsm_x4(bh, bb + 2 * TILEB);
            ldsm_x4(bl, bb + 3 * TILEB);
#pragma unroll
            for (int mt = 0; mt < 4; mt++) {
                mma16816(acc[mt][2 * np + 0], afr[0][mt], &bh[0]);
                mma16816(acc[mt][2 * np + 1], afr[0][mt], &bh[2]);
                mma16816(acc[mt][2 * np + 0], afr[0][mt], &bl[0]);
                mma16816(acc[mt][2 * np + 1], afr[0][mt], &bl[2]);
                mma16816(acc[mt][2 * np + 0], afr[1][mt], &bh[0]);
                mma16816(acc[mt][2 * np + 1], afr[1][mt], &bh[2]);
            }
        }
    }

    const int g   = lane >> 2;
    const int tig = lane & 3;
#pragma unroll
    for (int mt = 0; mt < 4; mt++) {
        int r = row0 + warp_m + mt * 16 + g;
#pragma unroll
        for (int nt = 0; nt < 8; nt++) {
            int col = col0 + warp_n + nt * 8 + 2 * tig;
            if (SPLIT_OUT) {
                uint32_t hw, lw;
                split_pair(acc[mt][nt][0], acc[mt][nt][1], hw, lw);
                *(uint32_t*)(Ch + (size_t)z * SLOT + (size_t)r * EDIM + col) = hw;
                *(uint32_t*)(Cl + (size_t)z * SLOT + (size_t)r * EDIM + col) = lw;
                split_pair(acc[mt][nt][2], acc[mt][nt][3], hw, lw);
                *(uint32_t*)(Ch + (size_t)z * SLOT + (size_t)(r + 8) * EDIM + col) = hw;
                *(uint32_t*)(Cl + (size_t)z * SLOT + (size_t)(r + 8) * EDIM + col) = lw;
            } else {
                float bx = bias[col], by = bias[col + 1];
                *(float2*)(C + (size_t)r * EDIM + col) =
                    make_float2(acc[mt][nt][0] + bx, acc[mt][nt][1] + by);
                *(float2*)(C + (size_t)(r + 8) * EDIM + col) =
                    make_float2(acc[mt][nt][2] + bx, acc[mt][nt][3] + by);
            }
        }
    }
}

// ---------------------------------------------------------------------------
// Flash attention on HMMA. 4 warps x 32 q-rows (Br=128), Bc=64, fused
// per-16-key block, 3-stage cp.async ring, ONE barrier per tile, 2 CTAs/SM.
// Softmax over UNSCALED scores (faithful reference bug), no running max.
// ---------------------------------------------------------------------------
#define KROWB    144
#define KTILE    (64 * KROWB)                // 9216
#define QTILE    (128 * KROWB)               // 18432
#define FA_STAGE (4 * KTILE)                 // 36864
#define FA_STAGES 3
#define FA_SMEM  (FA_STAGES * FA_STAGE)      // 110592

__global__ __launch_bounds__(128, 2)
void flash_hmma(const __nv_bfloat16* __restrict__ ph, const __nv_bfloat16* __restrict__ pl,
                __nv_bfloat16* __restrict__ oh, __nv_bfloat16* __restrict__ ol)
{
    extern __shared__ char sm[];
    const uint32_t sb = smem_u32(sm);
    const int tid  = threadIdx.x;
    const int wid  = tid >> 5;
    const int lane = tid & 31;
    const int warp_m = wid * 32;

    const int qt = blockIdx.x;
    const int h  = blockIdx.y;
    const int b  = blockIdx.z;
    const size_t baseRow = (size_t)b * SEQ;
    const int hcol = h * HD;

    const __nv_bfloat16* qh = ph;
    const __nv_bfloat16* ql = pl;
    const __nv_bfloat16* kh = ph + SLOT;
    const __nv_bfloat16* kl = pl + SLOT;
    const __nv_bfloat16* vh = ph + 2 * SLOT;
    const __nv_bfloat16* vl = pl + 2 * SLOT;

    const uint32_t a_loff  = (uint32_t)(lane & 15) * KROWB + ((lane & 16) ? 16u : 0u);
    const uint32_t bk_loff = (uint32_t)((lane & 7) + ((lane & 16) ? 8 : 0)) * KROWB
                           + ((lane & 8) ? 16u : 0u);
    const uint32_t bv_loff = (uint32_t)((lane & 7) + ((lane & 8) ? 8 : 0)) * KROWB
                           + ((lane & 16) ? 16u : 0u);

    // ---- stage Q (hi at 0, lo at QTILE), pull A-fragments ----
    {
#pragma unroll
        for (int it = 0; it < 8; it++) {
            int c = tid + it * 128;          // 0..1023
            int row = c >> 3, ch = c & 7;
            uint32_t doff = (uint32_t)row * KROWB + (uint32_t)ch * 16;
            size_t ga = (baseRow + qt * 128 + row) * EDIM + hcol + ch * 8;
            cp16(sb + doff,         qh + ga);
            cp16(sb + QTILE + doff, ql + ga);
        }
        CP_COMMIT();
        CP_WAIT(0);
        __syncthreads();
    }
    uint32_t qfr[2][4][2][4];   // [split][kstep][mt][frag]
#pragma unroll
    for (int sp = 0; sp < 2; sp++)
#pragma unroll
        for (int ks = 0; ks < 4; ks++)
#pragma unroll
            for (int mt = 0; mt < 2; mt++)
                ldsm_x4(qfr[sp][ks][mt],
                        sb + sp * QTILE + (uint32_t)(warp_m + mt * 16) * KROWB
                             + ks * 32 + a_loff);
    __syncthreads();

    auto issue_kv = [&](int t) {
        const uint32_t base = sb + (uint32_t)(t % 3) * FA_STAGE;
#pragma unroll
        for (int it = 0; it < 4; it++) {
            int c = tid + it * 128;          // 0..511
            int row = c >> 3, ch = c & 7;
            uint32_t doff = (uint32_t)row * KROWB + (uint32_t)ch * 16;
            size_t ga = (baseRow + t * 64 + row) * EDIM + hcol + ch * 8;
            cp16(base + doff,             kh + ga);
            cp16(base + KTILE + doff,     kl + ga);
            cp16(base + 2 * KTILE + doff, vh + ga);
            cp16(base + 3 * KTILE + doff, vl + ga);
        }
        CP_COMMIT();
    };

    issue_kv(0);
    issue_kv(1);

    float Oa[2][8][4];
#pragma unroll
    for (int mt = 0; mt < 2; mt++)
#pragma unroll
        for (int i = 0; i < 8; i++)
#pragma unroll
            for (int c = 0; c < 4; c++) Oa[mt][i][c] = 0.f;
    float lsum[2][2] = {{0.f, 0.f}, {0.f, 0.f}};

    const int NT = SEQ / 64;   // 32
    for (int t = 0; t < NT; t++) {
        if (t + 2 <= NT) { CP_WAIT(1); } else { CP_WAIT(0); }
        __syncthreads();
        if (t + 2 < NT) issue_kv(t + 2);     // target consumed at t-1: safe

        const uint32_t bs = sb + (uint32_t)(t % 3) * FA_STAGE;
        float rs[2][2] = {{0.f, 0.f}, {0.f, 0.f}};

        // fused per-16-key block: QK -> exp -> pack -> PV
#pragma unroll
        for (int ng = 0; ng < 4; ng++) {
            float S[2][2][4];
#pragma unroll
            for (int mt = 0; mt < 2; mt++)
#pragma unroll
                for (int tt = 0; tt < 2; tt++)
#pragma unroll
                    for (int c = 0; c < 4; c++) S[mt][tt][c] = 0.f;

#pragma unroll
            for (int ks = 0; ks < 4; ks++) {
                uint32_t b1[4], b2[4];
                uint32_t kb = bs + (uint32_t)(ng * 16) * KROWB + ks * 32 + bk_loff;
                ldsm_x4(b1, kb);
                ldsm_x4(b2, kb + KTILE);
#pragma unroll
                for (int mt = 0; mt < 2; mt++) {
                    mma16816(S[mt][0], qfr[0][ks][mt], &b1[0]);
                    mma16816(S[mt][1], qfr[0][ks][mt], &b1[2]);
                    mma16816(S[mt][0], qfr[0][ks][mt], &b2[0]);
                    mma16816(S[mt][1], qfr[0][ks][mt], &b2[2]);
                    mma16816(S[mt][0], qfr[1][ks][mt], &b1[0]);
                    mma16816(S[mt][1], qfr[1][ks][mt], &b1[2]);
                }
            }

            uint32_t p1[2][4], p2[2][4];
#pragma unroll
            for (int mt = 0; mt < 2; mt++) {
#pragma unroll
                for (int tt = 0; tt < 2; tt++) {
                    S[mt][tt][0] = __expf(S[mt][tt][0]);
                    S[mt][tt][1] = __expf(S[mt][tt][1]);
                    S[mt][tt][2] = __expf(S[mt][tt][2]);
                    S[mt][tt][3] = __expf(S[mt][tt][3]);
                    rs[mt][0] += S[mt][tt][0] + S[mt][tt][1];
                    rs[mt][1] += S[mt][tt][2] + S[mt][tt][3];
                }
#pragma unroll
                for (int tt = 0; tt < 2; tt++)
#pragma unroll
                    for (int hl = 0; hl < 2; hl++)
                        split_pair(S[mt][tt][2 * hl + 0], S[mt][tt][2 * hl + 1],
                                   p1[mt][tt * 2 + hl], p2[mt][tt * 2 + hl]);
            }

#pragma unroll
            for (int dg = 0; dg < 4; dg++) {
                uint32_t v1[4], v2[4];
                uint32_t vb = bs + 2 * KTILE + (uint32_t)(ng * 16) * KROWB
                            + dg * 32 + bv_loff;
                ldsm_x4_t(v1, vb);
                ldsm_x4_t(v2, vb + KTILE);
#pragma unroll
                for (int mt = 0; mt < 2; mt++) {
                    mma16816(Oa[mt][dg * 2 + 0], p1[mt], &v1[0]);
                    mma16816(Oa[mt][dg * 2 + 1], p1[mt], &v1[2]);
                    mma16816(Oa[mt][dg * 2 + 0], p1[mt], &v2[0]);
                    mma16816(Oa[mt][dg * 2 + 1], p1[mt], &v2[2]);
                    mma16816(Oa[mt][dg * 2 + 0], p2[mt], &v1[0]);
                    mma16816(Oa[mt][dg * 2 + 1], p2[mt], &v1[2]);
                }
            }
        }

#pragma unroll
        for (int mt = 0; mt < 2; mt++)
#pragma unroll
            for (int j = 0; j < 2; j++) {
                float r = rs[mt][j];
                r += __shfl_xor_sync(0xffffffffu, r, 1);
                r += __shfl_xor_sync(0xffffffffu, r, 2);
                lsum[mt][j] += r;
            }
    }

    // ---- normalize & write split output into slot 0 of (oh, ol) ----
    const int g   = lane >> 2;
    const int tq2 = (lane & 3) * 2;
#pragma unroll
    for (int mt = 0; mt < 2; mt++) {
        const float inv0 = 1.0f / lsum[mt][0];
        const float inv1 = 1.0f / lsum[mt][1];
        const size_t r0 = (baseRow + qt * 128 + warp_m + mt * 16 + g) * EDIM + hcol;
        const size_t r1 = r0 + (size_t)8 * EDIM;
#pragma unroll
        for (int i = 0; i < 8; i++) {
            int d = i * 8 + tq2;
            uint32_t hw, lw;
            split_pair(Oa[mt][i][0] * inv0, Oa[mt][i][1] * inv0, hw, lw);
            *(uint32_t*)(oh + r0 + d) = hw;
            *(uint32_t*)(ol + r0 + d) = lw;
            split_pair(Oa[mt][i][2] * inv1, Oa[mt][i][3] * inv1, hw, lw);
            *(uint32_t*)(oh + r1 + d) = hw;
            *(uint32_t*)(ol + r1 + d) = lw;
        }
    }
}

// ---------------------------------------------------------------------------
extern "C" void kernel_launch(void* const* d_in, const int* in_sizes, int n_in,
                              void* d_out, int out_size)
{
    (void)in_sizes; (void)n_in; (void)out_size;

    const float* Q  = (const float*)d_in[0];
    const float* K  = (const float*)d_in[1];
    const float* V  = (const float*)d_in[2];
    const float* Wq = (const float*)d_in[3];
    const float* Wk = (const float*)d_in[4];
    const float* Wv = (const float*)d_in[5];
    const float* Wo = (const float*)d_in[6];
    const float* bo = (const float*)d_in[7];
    float* out = (float*)d_out;

    __nv_bfloat16 *xh, *xl, *phb, *plb, *wh, *wl;
    cudaGetSymbolAddress((void**)&xh, g_xh);
    cudaGetSymbolAddress((void**)&xl, g_xl);
    cudaGetSymbolAddress((void**)&phb, g_ph);
    cudaGetSymbolAddress((void**)&plb, g_pl);
    cudaGetSymbolAddress((void**)&wh, g_wh);
    cudaGetSymbolAddress((void**)&wl, g_wl);

    cudaFuncSetAttribute(gemm_hmma<true>,
                         cudaFuncAttributeMaxDynamicSharedMemorySize, GEMM_SMEM);
    cudaFuncSetAttribute(gemm_hmma<false>,
                         cudaFuncAttributeMaxDynamicSharedMemorySize, GEMM_SMEM);
    cudaFuncSetAttribute(flash_hmma,
                         cudaFuncAttributeMaxDynamicSharedMemorySize, FA_SMEM);

    const int nA4 = MTOT * EDIM / 4;
    const int nW4 = EDIM * EDIM / 4;

    split_in_kernel<<<dim3(nA4 / 256, 3), 256>>>(Q, K, V, xh, xl, nA4);
    split_w_kernel<<<dim3(nW4 / 256, 4), 256>>>(Wq, Wk, Wv, Wo, wh, wl, nW4);

    gemm_hmma<true><<<dim3(EDIM / 128, MTOT / 128, 3), 128, GEMM_SMEM>>>(
        xh, xl, wh, wl, nullptr, nullptr, phb, plb);

    flash_hmma<<<dim3(SEQ / 128, NH, NB), 128, FA_SMEM>>>(phb, plb, xh, xl);

    gemm_hmma<false><<<dim3(EDIM / 128, MTOT / 128, 1), 128, GEMM_SMEM>>>(
        xh, xl, wh + 3 * WSLOT, wl + 3 * WSLOT, bo, out, nullptr, nullptr);
}